// round 1
// baseline (speedup 1.0000x reference)
#include <cuda_runtime.h>
#include <math.h>

// ---------------- problem constants ----------------
#define Bn   4
#define Sn   512
#define Dm   1024
#define Hn   16
#define HD   64
#define En   8
#define FF   2048
#define Ln   2
#define VT   32000
#define TOK  (Bn*Sn)      // 2048 tokens

// ---------------- device scratch (no allocations allowed) ----------------
__device__ float g_x[TOK*Dm];
__device__ float g_y[TOK*Dm];
__device__ float g_lin0[TOK*Dm];
__device__ float g_lin1[TOK*Dm];
__device__ float g_lin2[TOK*Dm];
__device__ float g_q[TOK*Dm];
__device__ float g_k[TOK*Dm];
__device__ float g_v[TOK*Dm];
__device__ float g_sc[(size_t)Bn*Hn*Sn*Sn];     // 67 MB scores
__device__ float g_att[TOK*Dm];
__device__ float g_att_t[TOK*Dm];
__device__ float g_proj[TOK*Dm];
__device__ float g_h1[(size_t)TOK*FF];
__device__ float g_moe0[TOK*Dm];
__device__ float g_moe1[TOK*Dm];
__device__ float g_gate[TOK*En];
__device__ float g_topw[TOK*2];
__device__ int   g_list[En*TOK];
__device__ int   g_cnt[En];
__device__ float g_cos[Sn*HD];
__device__ float g_sin[Sn*HD];

// ---------------- RoPE tables (double precision to match numpy f64) ----------------
__global__ void rope_init_kernel() {
    int idx = blockIdx.x * blockDim.x + threadIdx.x;
    if (idx >= Sn * HD) return;
    int s = idx >> 6;
    int j = idx & 63;
    int jj = j & 31;
    double inv = pow(10000.0, -((double)(2 * jj)) / 64.0);
    double ang = (double)s * inv;
    g_cos[idx] = (float)cos(ang);
    g_sin[idx] = (float)sin(ang);
}

// ---------------- embedding gather ----------------
__global__ void embed_kernel(const int* __restrict__ ids, const float* __restrict__ table,
                             float* __restrict__ out) {
    int idx = blockIdx.x * blockDim.x + threadIdx.x;   // TOK*Dm threads
    int t = idx >> 10;
    int d = idx & 1023;
    out[idx] = table[(long long)ids[t] * Dm + d];
}

// ---------------- generic SGEMM: C = alpha*(A@W) + bias, optional relu, batched ----------------
__global__ void sgemm_kernel(const float* __restrict__ A, const float* __restrict__ W,
                             const float* __restrict__ bias, float* __restrict__ C,
                             int M, int N, int K, int relu, float alpha,
                             long long sA, long long sW, long long sC) {
    A += (long long)blockIdx.z * sA;
    W += (long long)blockIdx.z * sW;
    C += (long long)blockIdx.z * sC;
    const int tid = threadIdx.x;
    const int bm = blockIdx.y * 64, bn = blockIdx.x * 64;
    __shared__ float As[16][68];
    __shared__ float Ws[16][68];
    float acc[4][4] = {};
    const int ty = tid >> 4, tx = tid & 15;
    for (int k0 = 0; k0 < K; k0 += 16) {
#pragma unroll
        for (int i = 0; i < 4; i++) {
            int e = tid + i * 256;
            int r = e >> 4, kk = e & 15;
            int gr = bm + r, gk = k0 + kk;
            As[kk][r] = (gr < M && gk < K) ? A[(long long)gr * K + gk] : 0.f;
        }
#pragma unroll
        for (int i = 0; i < 4; i++) {
            int e = tid + i * 256;
            int kk = e >> 6, c = e & 63;
            int gk = k0 + kk, gc = bn + c;
            Ws[kk][c] = (gk < K && gc < N) ? W[(long long)gk * N + gc] : 0.f;
        }
        __syncthreads();
#pragma unroll
        for (int kk = 0; kk < 16; kk++) {
            float4 a4 = *(const float4*)&As[kk][ty * 4];
            float4 b4 = *(const float4*)&Ws[kk][tx * 4];
            float av[4] = {a4.x, a4.y, a4.z, a4.w};
            float bv[4] = {b4.x, b4.y, b4.z, b4.w};
#pragma unroll
            for (int i = 0; i < 4; i++)
#pragma unroll
                for (int j = 0; j < 4; j++) acc[i][j] += av[i] * bv[j];
        }
        __syncthreads();
    }
#pragma unroll
    for (int i = 0; i < 4; i++) {
        int r = bm + ty * 4 + i;
        if (r >= M) continue;
#pragma unroll
        for (int j = 0; j < 4; j++) {
            int c = bn + tx * 4 + j;
            if (c >= N) continue;
            float v = acc[i][j] * alpha + (bias ? bias[c] : 0.f);
            if (relu) v = fmaxf(v, 0.f);
            C[(long long)r * N + c] = v;
        }
    }
}

// ---------------- NT GEMM for Q@K^T (batched, dims fixed multiples of 64) ----------------
__global__ void sgemm_nt_kernel(const float* __restrict__ A, const float* __restrict__ B,
                                float* __restrict__ C, int M, int N, int K, float alpha,
                                long long sA, long long sB, long long sC) {
    A += (long long)blockIdx.z * sA;
    B += (long long)blockIdx.z * sB;
    C += (long long)blockIdx.z * sC;
    const int tid = threadIdx.x;
    const int bm = blockIdx.y * 64, bn = blockIdx.x * 64;
    __shared__ float As[16][68];
    __shared__ float Bs[16][68];
    float acc[4][4] = {};
    const int ty = tid >> 4, tx = tid & 15;
    for (int k0 = 0; k0 < K; k0 += 16) {
#pragma unroll
        for (int i = 0; i < 4; i++) {
            int e = tid + i * 256;
            int r = e >> 4, kk = e & 15;
            As[kk][r] = A[(long long)(bm + r) * K + k0 + kk];
            Bs[kk][r] = B[(long long)(bn + r) * K + k0 + kk];
        }
        __syncthreads();
#pragma unroll
        for (int kk = 0; kk < 16; kk++) {
            float4 a4 = *(const float4*)&As[kk][ty * 4];
            float4 b4 = *(const float4*)&Bs[kk][tx * 4];
            float av[4] = {a4.x, a4.y, a4.z, a4.w};
            float bv[4] = {b4.x, b4.y, b4.z, b4.w};
#pragma unroll
            for (int i = 0; i < 4; i++)
#pragma unroll
                for (int j = 0; j < 4; j++) acc[i][j] += av[i] * bv[j];
        }
        __syncthreads();
    }
#pragma unroll
    for (int i = 0; i < 4; i++)
#pragma unroll
        for (int j = 0; j < 4; j++)
            C[(long long)(bm + ty * 4 + i) * N + bn + tx * 4 + j] = acc[i][j] * alpha;
}

// ---------------- RoPE + [tok,D] -> [b,h,s,hd] permute ----------------
__global__ void rope_perm_kernel(const float* __restrict__ lin, float* __restrict__ out,
                                 int do_rope) {
    int idx = blockIdx.x * blockDim.x + threadIdx.x;   // TOK*Dm
    int t = idx >> 10;
    int col = idx & 1023;
    int b = t >> 9;
    int s = t & 511;
    int h = col >> 6;
    int d = col & 63;
    float v = lin[idx];
    float o = v;
    if (do_rope) {
        float other = (d < 32) ? -lin[idx + 32] : lin[idx - 32];
        o = v * g_cos[s * 64 + d] + other * g_sin[s * 64 + d];
    }
    out[((long long)(b * Hn + h) * Sn + s) * HD + d] = o;
}

// ---------------- [b,h,s,hd] -> [tok,D] permute ----------------
__global__ void perm_back_kernel(const float* __restrict__ att, float* __restrict__ out) {
    int idx = blockIdx.x * blockDim.x + threadIdx.x;   // indexes bhsd layout
    int d = idx & 63;
    int s = (idx >> 6) & 511;
    int h = (idx >> 15) & 15;
    int b = idx >> 19;
    out[(long long)(b * Sn + s) * Dm + h * HD + d] = att[idx];
}

// ---------------- row softmax with optional causal mask ----------------
__global__ void softmax_rows_kernel(float* __restrict__ sc, int causal) {
    int row = blockIdx.x;                                // 0..511 (query pos)
    long long base = ((long long)blockIdx.y * Sn + row) * Sn;
    int tid = threadIdx.x;
    float v0 = sc[base + tid];
    float v1 = sc[base + tid + 256];
    if (causal) {
        if (tid > row) v0 = -1e9f;
        if (tid + 256 > row) v1 = -1e9f;
    }
    __shared__ float red[256];
    float m = fmaxf(v0, v1);
    red[tid] = m;
    __syncthreads();
    for (int s = 128; s > 0; s >>= 1) {
        if (tid < s) red[tid] = fmaxf(red[tid], red[tid + s]);
        __syncthreads();
    }
    m = red[0];
    __syncthreads();
    float e0 = expf(v0 - m), e1 = expf(v1 - m);
    red[tid] = e0 + e1;
    __syncthreads();
    for (int s = 128; s > 0; s >>= 1) {
        if (tid < s) red[tid] += red[tid + s];
        __syncthreads();
    }
    float inv = 1.f / red[0];
    sc[base + tid] = e0 * inv;
    sc[base + tid + 256] = e1 * inv;
}

// ---------------- fused residual add(+add2) + layernorm ----------------
__global__ void add_ln_kernel(const float* __restrict__ x, const float* __restrict__ a,
                              const float* __restrict__ a2,
                              const float* __restrict__ g, const float* __restrict__ b,
                              float* __restrict__ out) {
    int t = blockIdx.x;
    int tid = threadIdx.x;
    long long base = (long long)t * Dm;
    float v[4];
#pragma unroll
    for (int i = 0; i < 4; i++) {
        int c = tid + i * 256;
        float s = x[base + c] + a[base + c];
        if (a2) s += a2[base + c];
        v[i] = s;
    }
    __shared__ float red[256];
    red[tid] = v[0] + v[1] + v[2] + v[3];
    __syncthreads();
    for (int k = 128; k > 0; k >>= 1) {
        if (tid < k) red[tid] += red[tid + k];
        __syncthreads();
    }
    float mu = red[0] * (1.f / Dm);
    __syncthreads();
    float q = 0.f;
#pragma unroll
    for (int i = 0; i < 4; i++) { float d = v[i] - mu; q += d * d; }
    red[tid] = q;
    __syncthreads();
    for (int k = 128; k > 0; k >>= 1) {
        if (tid < k) red[tid] += red[tid + k];
        __syncthreads();
    }
    float var = red[0] * (1.f / Dm);
    float inv = rsqrtf(var + 1e-5f);
#pragma unroll
    for (int i = 0; i < 4; i++) {
        int c = tid + i * 256;
        out[base + c] = (v[i] - mu) * inv * g[c] + b[c];
    }
}

// ---------------- MoE gating: softmax over 8, top-2, renorm, route lists ----------------
__global__ void zero_cnt_kernel(int* c) { if (threadIdx.x < En) c[threadIdx.x] = 0; }

__global__ void gate_route_kernel(const float* __restrict__ logits, float* __restrict__ topw,
                                  int* __restrict__ list, int* __restrict__ cnt) {
    int t = blockIdx.x * blockDim.x + threadIdx.x;
    if (t >= TOK) return;
    float p[En];
    float m = -1e30f;
#pragma unroll
    for (int e = 0; e < En; e++) { p[e] = logits[t * En + e]; m = fmaxf(m, p[e]); }
    float s = 0.f;
#pragma unroll
    for (int e = 0; e < En; e++) { p[e] = expf(p[e] - m); s += p[e]; }
    float invs = 1.f / s;
#pragma unroll
    for (int e = 0; e < En; e++) p[e] *= invs;
    int i0 = 0;
#pragma unroll
    for (int e = 1; e < En; e++) if (p[e] > p[i0]) i0 = e;
    int i1 = (i0 == 0) ? 1 : 0;
#pragma unroll
    for (int e = 0; e < En; e++) if (e != i0 && p[e] > p[i1]) i1 = e;
    float s2 = p[i0] + p[i1];
    topw[t * 2 + 0] = p[i0] / s2;
    topw[t * 2 + 1] = p[i1] / s2;
    int pos = atomicAdd(&cnt[i0], 1);
    list[i0 * TOK + pos] = t * 2 + 0;
    pos = atomicAdd(&cnt[i1], 1);
    list[i1 * TOK + pos] = t * 2 + 1;
}

// ---------------- expert GEMM 1: gathered rows, H1 = relu(Xg @ W1 + b1) ----------------
__global__ void moe_gemm1_kernel(const float* __restrict__ X, const float* __restrict__ W,
                                 const float* __restrict__ bias, float* __restrict__ H1,
                                 const int* __restrict__ list, const int* __restrict__ cnt) {
    const int nrows = *cnt;
    const int bm = blockIdx.y * 64, bn = blockIdx.x * 64;
    if (bm >= nrows) return;
    const int tid = threadIdx.x;
    __shared__ int toks[64];
    __shared__ float As[16][68];
    __shared__ float Ws[16][68];
    if (tid < 64) {
        int gr = bm + tid;
        toks[tid] = (gr < nrows) ? (list[gr] >> 1) : 0;
    }
    __syncthreads();
    float acc[4][4] = {};
    const int ty = tid >> 4, tx = tid & 15;
    for (int k0 = 0; k0 < Dm; k0 += 16) {
#pragma unroll
        for (int i = 0; i < 4; i++) {
            int e = tid + i * 256;
            int r = e >> 4, kk = e & 15;
            As[kk][r] = X[(long long)toks[r] * Dm + k0 + kk];
        }
#pragma unroll
        for (int i = 0; i < 4; i++) {
            int e = tid + i * 256;
            int kk = e >> 6, c = e & 63;
            Ws[kk][c] = W[(long long)(k0 + kk) * FF + bn + c];
        }
        __syncthreads();
#pragma unroll
        for (int kk = 0; kk < 16; kk++) {
            float4 a4 = *(const float4*)&As[kk][ty * 4];
            float4 b4 = *(const float4*)&Ws[kk][tx * 4];
            float av[4] = {a4.x, a4.y, a4.z, a4.w};
            float bv[4] = {b4.x, b4.y, b4.z, b4.w};
#pragma unroll
            for (int i = 0; i < 4; i++)
#pragma unroll
                for (int j = 0; j < 4; j++) acc[i][j] += av[i] * bv[j];
        }
        __syncthreads();
    }
#pragma unroll
    for (int i = 0; i < 4; i++) {
        int gr = bm + ty * 4 + i;
        if (gr >= nrows) continue;
#pragma unroll
        for (int j = 0; j < 4; j++) {
            int c = bn + tx * 4 + j;
            H1[(long long)gr * FF + c] = fmaxf(acc[i][j] + bias[c], 0.f);
        }
    }
}

// ---------------- expert GEMM 2: out_slot[token] = w * (H1 @ W2 + b2) ----------------
__global__ void moe_gemm2_kernel(const float* __restrict__ H1, const float* __restrict__ W,
                                 const float* __restrict__ bias,
                                 float* __restrict__ out0, float* __restrict__ out1,
                                 const float* __restrict__ topw,
                                 const int* __restrict__ list, const int* __restrict__ cnt) {
    const int nrows = *cnt;
    const int bm = blockIdx.y * 64, bn = blockIdx.x * 64;
    if (bm >= nrows) return;
    const int tid = threadIdx.x;
    __shared__ int ents[64];
    __shared__ float As[16][68];
    __shared__ float Ws[16][68];
    if (tid < 64) {
        int gr = bm + tid;
        ents[tid] = (gr < nrows) ? list[gr] : -1;
    }
    __syncthreads();
    float acc[4][4] = {};
    const int ty = tid >> 4, tx = tid & 15;
    for (int k0 = 0; k0 < FF; k0 += 16) {
#pragma unroll
        for (int i = 0; i < 4; i++) {
            int e = tid + i * 256;
            int r = e >> 4, kk = e & 15;
            As[kk][r] = H1[(long long)(bm + r) * FF + k0 + kk];
        }
#pragma unroll
        for (int i = 0; i < 4; i++) {
            int e = tid + i * 256;
            int kk = e >> 6, c = e & 63;
            Ws[kk][c] = W[(long long)(k0 + kk) * Dm + bn + c];
        }
        __syncthreads();
#pragma unroll
        for (int kk = 0; kk < 16; kk++) {
            float4 a4 = *(const float4*)&As[kk][ty * 4];
            float4 b4 = *(const float4*)&Ws[kk][tx * 4];
            float av[4] = {a4.x, a4.y, a4.z, a4.w};
            float bv[4] = {b4.x, b4.y, b4.z, b4.w};
#pragma unroll
            for (int i = 0; i < 4; i++)
#pragma unroll
                for (int j = 0; j < 4; j++) acc[i][j] += av[i] * bv[j];
        }
        __syncthreads();
    }
#pragma unroll
    for (int i = 0; i < 4; i++) {
        int ent = ents[ty * 4 + i];
        if (ent < 0) continue;
        int t = ent >> 1;
        float w = topw[ent];
        float* o = (ent & 1) ? out1 : out0;
#pragma unroll
        for (int j = 0; j < 4; j++) {
            int c = bn + tx * 4 + j;
            o[(long long)t * Dm + c] = w * (acc[i][j] + bias[c]);
        }
    }
}

// ================= host orchestration =================
struct DevPtrs {
    float *x, *y, *lin0, *lin1, *lin2, *q, *k, *v, *sc, *att, *att_t, *proj;
    float *h1, *moe0, *moe1, *gate, *topw;
    int *list, *cnt;
};

static void gemm(const float* A, const float* W, const float* bias, float* C,
                 int M, int N, int K, int relu, float alpha = 1.f, int batch = 1,
                 long long sA = 0, long long sW = 0, long long sC = 0) {
    dim3 g((N + 63) / 64, (M + 63) / 64, batch);
    sgemm_kernel<<<g, 256>>>(A, W, bias, C, M, N, K, relu, alpha, sA, sW, sC);
}

static void run_mha(DevPtrs& P, float* xio, const float* kvin,
                    const float* wqkv, const float* bqkv,
                    const float* wo, const float* bo,
                    const float* lng, const float* lnb, int causal) {
    gemm(xio,  wqkv,               bqkv,          P.lin0, TOK, Dm, Dm, 0);
    gemm(kvin, wqkv + Dm * Dm,     bqkv + Dm,     P.lin1, TOK, Dm, Dm, 0);
    gemm(kvin, wqkv + 2 * Dm * Dm, bqkv + 2 * Dm, P.lin2, TOK, Dm, Dm, 0);
    int nb = (TOK * Dm) / 256;
    rope_perm_kernel<<<nb, 256>>>(P.lin0, P.q, 1);
    rope_perm_kernel<<<nb, 256>>>(P.lin1, P.k, 1);
    rope_perm_kernel<<<nb, 256>>>(P.lin2, P.v, 0);
    dim3 gs(Sn / 64, Sn / 64, Bn * Hn);
    sgemm_nt_kernel<<<gs, 256>>>(P.q, P.k, P.sc, Sn, Sn, HD, 0.125f,
                                 (long long)Sn * HD, (long long)Sn * HD, (long long)Sn * Sn);
    softmax_rows_kernel<<<dim3(Sn, Bn * Hn), 256>>>(P.sc, causal);
    gemm(P.sc, P.v, nullptr, P.att, Sn, HD, Sn, 0, 1.f, Bn * Hn,
         (long long)Sn * Sn, (long long)Sn * HD, (long long)Sn * HD);
    perm_back_kernel<<<nb, 256>>>(P.att, P.att_t);
    gemm(P.att_t, wo, bo, P.proj, TOK, Dm, Dm, 0);
    add_ln_kernel<<<TOK, 256>>>(xio, P.proj, nullptr, lng, lnb, xio);
}

static void run_moe(DevPtrs& P, float* xio, const float* gw, const float* gb,
                    const float* w1, const float* b1, const float* w2, const float* b2,
                    const float* lng, const float* lnb) {
    gemm(xio, gw, gb, P.gate, TOK, En, Dm, 0);
    zero_cnt_kernel<<<1, 32>>>(P.cnt);
    gate_route_kernel<<<TOK / 256, 256>>>(P.gate, P.topw, P.list, P.cnt);
    for (int e = 0; e < En; e++) {
        moe_gemm1_kernel<<<dim3(FF / 64, TOK / 64), 256>>>(
            xio, w1 + (long long)e * Dm * FF, b1 + e * FF, P.h1, P.list + e * TOK, P.cnt + e);
        moe_gemm2_kernel<<<dim3(Dm / 64, TOK / 64), 256>>>(
            P.h1, w2 + (long long)e * FF * Dm, b2 + e * Dm, P.moe0, P.moe1, P.topw,
            P.list + e * TOK, P.cnt + e);
    }
    add_ln_kernel<<<TOK, 256>>>(xio, P.moe0, P.moe1, lng, lnb, xio);
}

extern "C" void kernel_launch(void* const* d_in, const int* in_sizes, int n_in,
                              void* d_out, int out_size) {
    (void)in_sizes; (void)n_in; (void)out_size;
    const int*   src           = (const int*)  d_in[0];
    const int*   tgt           = (const int*)  d_in[1];
    const float* emb_src       = (const float*)d_in[2];
    const float* emb_tgt       = (const float*)d_in[3];
    const float* enc_wqkv      = (const float*)d_in[4];
    const float* enc_bqkv      = (const float*)d_in[5];
    const float* enc_wo        = (const float*)d_in[6];
    const float* enc_bo        = (const float*)d_in[7];
    const float* enc_gate_w    = (const float*)d_in[8];
    const float* enc_gate_b    = (const float*)d_in[9];
    const float* enc_w1        = (const float*)d_in[10];
    const float* enc_b1        = (const float*)d_in[11];
    const float* enc_w2        = (const float*)d_in[12];
    const float* enc_b2        = (const float*)d_in[13];
    const float* enc_ln        = (const float*)d_in[14];
    const float* dec_self_wqkv = (const float*)d_in[15];
    const float* dec_self_bqkv = (const float*)d_in[16];
    const float* dec_self_wo   = (const float*)d_in[17];
    const float* dec_self_bo   = (const float*)d_in[18];
    const float* dec_cross_wqkv= (const float*)d_in[19];
    const float* dec_cross_bqkv= (const float*)d_in[20];
    const float* dec_cross_wo  = (const float*)d_in[21];
    const float* dec_cross_bo  = (const float*)d_in[22];
    const float* dec_gate_w    = (const float*)d_in[23];
    const float* dec_gate_b    = (const float*)d_in[24];
    const float* dec_w1        = (const float*)d_in[25];
    const float* dec_b1        = (const float*)d_in[26];
    const float* dec_w2        = (const float*)d_in[27];
    const float* dec_b2        = (const float*)d_in[28];
    const float* dec_ln        = (const float*)d_in[29];
    const float* final_w       = (const float*)d_in[30];
    const float* final_b       = (const float*)d_in[31];
    float* out = (float*)d_out;

    DevPtrs P;
    cudaGetSymbolAddress((void**)&P.x, g_x);
    cudaGetSymbolAddress((void**)&P.y, g_y);
    cudaGetSymbolAddress((void**)&P.lin0, g_lin0);
    cudaGetSymbolAddress((void**)&P.lin1, g_lin1);
    cudaGetSymbolAddress((void**)&P.lin2, g_lin2);
    cudaGetSymbolAddress((void**)&P.q, g_q);
    cudaGetSymbolAddress((void**)&P.k, g_k);
    cudaGetSymbolAddress((void**)&P.v, g_v);
    cudaGetSymbolAddress((void**)&P.sc, g_sc);
    cudaGetSymbolAddress((void**)&P.att, g_att);
    cudaGetSymbolAddress((void**)&P.att_t, g_att_t);
    cudaGetSymbolAddress((void**)&P.proj, g_proj);
    cudaGetSymbolAddress((void**)&P.h1, g_h1);
    cudaGetSymbolAddress((void**)&P.moe0, g_moe0);
    cudaGetSymbolAddress((void**)&P.moe1, g_moe1);
    cudaGetSymbolAddress((void**)&P.gate, g_gate);
    cudaGetSymbolAddress((void**)&P.topw, g_topw);
    cudaGetSymbolAddress((void**)&P.list, g_list);
    cudaGetSymbolAddress((void**)&P.cnt, g_cnt);

    rope_init_kernel<<<(Sn * HD) / 256, 256>>>();

    // ---------- encoder ----------
    embed_kernel<<<(TOK * Dm) / 256, 256>>>(src, emb_src, P.x);
    for (int l = 0; l < Ln; l++) {
        run_mha(P, P.x, P.x,
                enc_wqkv + (long long)l * 3 * Dm * Dm, enc_bqkv + l * 3 * Dm,
                enc_wo + (long long)l * Dm * Dm, enc_bo + l * Dm,
                enc_ln + ((l * 2 + 0) * 2 + 0) * Dm, enc_ln + ((l * 2 + 0) * 2 + 1) * Dm, 0);
        run_moe(P, P.x,
                enc_gate_w + l * Dm * En, enc_gate_b + l * En,
                enc_w1 + (long long)l * En * Dm * FF, enc_b1 + l * En * FF,
                enc_w2 + (long long)l * En * FF * Dm, enc_b2 + l * En * Dm,
                enc_ln + ((l * 2 + 1) * 2 + 0) * Dm, enc_ln + ((l * 2 + 1) * 2 + 1) * Dm);
    }

    // ---------- decoder ----------
    embed_kernel<<<(TOK * Dm) / 256, 256>>>(tgt, emb_tgt, P.y);
    for (int l = 0; l < Ln; l++) {
        run_mha(P, P.y, P.y,
                dec_self_wqkv + (long long)l * 3 * Dm * Dm, dec_self_bqkv + l * 3 * Dm,
                dec_self_wo + (long long)l * Dm * Dm, dec_self_bo + l * Dm,
                dec_ln + ((l * 3 + 0) * 2 + 0) * Dm, dec_ln + ((l * 3 + 0) * 2 + 1) * Dm, 1);
        run_mha(P, P.y, P.x,
                dec_cross_wqkv + (long long)l * 3 * Dm * Dm, dec_cross_bqkv + l * 3 * Dm,
                dec_cross_wo + (long long)l * Dm * Dm, dec_cross_bo + l * Dm,
                dec_ln + ((l * 3 + 1) * 2 + 0) * Dm, dec_ln + ((l * 3 + 1) * 2 + 1) * Dm, 0);
        run_moe(P, P.y,
                dec_gate_w + l * Dm * En, dec_gate_b + l * En,
                dec_w1 + (long long)l * En * Dm * FF, dec_b1 + l * En * FF,
                dec_w2 + (long long)l * En * FF * Dm, dec_b2 + l * En * Dm,
                dec_ln + ((l * 3 + 2) * 2 + 0) * Dm, dec_ln + ((l * 3 + 2) * 2 + 1) * Dm);
    }

    // ---------- final projection ----------
    gemm(P.y, final_w, final_b, out, TOK, VT, Dm, 0);
}

// round 3
// speedup vs baseline: 1.0074x; 1.0074x over previous
#include <cuda_runtime.h>
#include <math.h>
#include <stdint.h>

// ---------------- problem constants ----------------
#define Bn   4
#define Sn   512
#define Dm   1024
#define Hn   16
#define HD   64
#define En   8
#define FF   2048
#define Ln   2
#define VT   32000
#define TOK  (Bn*Sn)      // 2048 tokens

// ---------------- device scratch (no allocations allowed) ----------------
__device__ float g_x[TOK*Dm];
__device__ float g_y[TOK*Dm];
__device__ float g_lin0[TOK*Dm];
__device__ float g_lin1[TOK*Dm];
__device__ float g_lin2[TOK*Dm];
__device__ float g_q[TOK*Dm];
__device__ float g_k[TOK*Dm];
__device__ float g_v[TOK*Dm];
__device__ float g_sc[(size_t)Bn*Hn*Sn*Sn];     // 67 MB scores
__device__ float g_att[TOK*Dm];
__device__ float g_att_t[TOK*Dm];
__device__ float g_proj[TOK*Dm];
__device__ float g_h1[(size_t)TOK*FF];
__device__ float g_moe0[TOK*Dm];
__device__ float g_moe1[TOK*Dm];
__device__ float g_gate[TOK*En];
__device__ float g_topw[TOK*2];
__device__ int   g_list[En*TOK];
__device__ int   g_cnt[En];
__device__ float g_cos[Sn*HD];
__device__ float g_sin[Sn*HD];

// ---------------- tf32 helpers ----------------
__device__ __forceinline__ uint32_t f2tf(float f) {
    uint32_t r;
    asm("cvt.rna.tf32.f32 %0, %1;" : "=r"(r) : "f"(f));
    return r;
}
// split x into tf32 hi + tf32 lo (3xTF32 compensation)
__device__ __forceinline__ void split_tf(float x, uint32_t& hi, uint32_t& lo) {
    hi = f2tf(x);
    lo = f2tf(x - __uint_as_float(hi));
}

__device__ __forceinline__ void mma_tf32(float* c, const uint32_t* a, const uint32_t* b) {
    asm volatile(
        "mma.sync.aligned.m16n8k8.row.col.f32.tf32.tf32.f32 "
        "{%0,%1,%2,%3}, {%4,%5,%6,%7}, {%8,%9}, {%0,%1,%2,%3};"
        : "+f"(c[0]), "+f"(c[1]), "+f"(c[2]), "+f"(c[3])
        : "r"(a[0]), "r"(a[1]), "r"(a[2]), "r"(a[3]), "r"(b[0]), "r"(b[1]));
}

// =====================================================================
// 3xTF32 MMA GEMM: C[M,N] = alpha*(A@B) + bias  (optional relu)
// Block 128x128, K-tile 16, 256 threads, 8 warps as 2(m) x 4(n),
// warp tile 64x32. hi/lo operand split -> near-fp32 accuracy.
// BT=0: B is [K,N] row-major.  BT=1: B is [N,K] row-major (NT gemm).
// M multiple of 128, K multiple of 16. N guarded (and all uses are /128).
// =====================================================================
#define KT 16

template<int BT>
__global__ void __launch_bounds__(256) mma_gemm_kernel(
    const float* __restrict__ A, const float* __restrict__ B,
    const float* __restrict__ bias, float* __restrict__ C,
    int M, int N, int K, int relu, float alpha,
    long long sA, long long sB, long long sC)
{
    constexpr int SST = 137;
    constexpr int BST = BT ? 137 : 136;
    A += (long long)blockIdx.z * sA;
    B += (long long)blockIdx.z * sB;
    C += (long long)blockIdx.z * sC;
    __shared__ uint32_t AsH[KT * SST];
    __shared__ uint32_t AsL[KT * SST];
    __shared__ uint32_t BsH[KT * BST];
    __shared__ uint32_t BsL[KT * BST];
    const int tid  = threadIdx.x;
    const int lane = tid & 31;
    const int warp = tid >> 5;
    const int wm = warp >> 2, wn = warp & 3;
    const int g  = lane >> 2, t4 = lane & 3;
    const int bm = blockIdx.y * 128, bn = blockIdx.x * 128;

    float acc[4][4][4];
#pragma unroll
    for (int i = 0; i < 4; i++)
#pragma unroll
        for (int j = 0; j < 4; j++)
#pragma unroll
            for (int q = 0; q < 4; q++) acc[i][j][q] = 0.f;

    for (int k0 = 0; k0 < K; k0 += KT) {
        // ---- A tile: global [m][k] -> smem [k][m] hi/lo ----
#pragma unroll
        for (int i = 0; i < 2; i++) {
            int fv = tid + i * 256;
            int m = fv >> 2, kq = fv & 3;
            const float4 v = *(const float4*)&A[(long long)(bm + m) * K + k0 + kq * 4];
            uint32_t h, l;
            split_tf(v.x, h, l); AsH[(kq*4+0)*SST+m] = h; AsL[(kq*4+0)*SST+m] = l;
            split_tf(v.y, h, l); AsH[(kq*4+1)*SST+m] = h; AsL[(kq*4+1)*SST+m] = l;
            split_tf(v.z, h, l); AsH[(kq*4+2)*SST+m] = h; AsL[(kq*4+2)*SST+m] = l;
            split_tf(v.w, h, l); AsH[(kq*4+3)*SST+m] = h; AsL[(kq*4+3)*SST+m] = l;
        }
        // ---- B tile ----
        if (BT == 0) {
#pragma unroll
            for (int i = 0; i < 2; i++) {
                int fv = tid + i * 256;
                int kk = fv >> 5, nq = fv & 31;
                int gc = bn + nq * 4;
                float4 v = make_float4(0.f, 0.f, 0.f, 0.f);
                if (gc < N) v = *(const float4*)&B[(long long)(k0 + kk) * N + gc];
                uint4 th, tl;
                split_tf(v.x, th.x, tl.x);
                split_tf(v.y, th.y, tl.y);
                split_tf(v.z, th.z, tl.z);
                split_tf(v.w, th.w, tl.w);
                *(uint4*)&BsH[kk * BST + nq * 4] = th;
                *(uint4*)&BsL[kk * BST + nq * 4] = tl;
            }
        } else {
#pragma unroll
            for (int i = 0; i < 2; i++) {
                int fv = tid + i * 256;
                int n = fv >> 2, kq = fv & 3;
                const float4 v = *(const float4*)&B[(long long)(bn + n) * K + k0 + kq * 4];
                uint32_t h, l;
                split_tf(v.x, h, l); BsH[(kq*4+0)*BST+n] = h; BsL[(kq*4+0)*BST+n] = l;
                split_tf(v.y, h, l); BsH[(kq*4+1)*BST+n] = h; BsL[(kq*4+1)*BST+n] = l;
                split_tf(v.z, h, l); BsH[(kq*4+2)*BST+n] = h; BsL[(kq*4+2)*BST+n] = l;
                split_tf(v.w, h, l); BsH[(kq*4+3)*BST+n] = h; BsL[(kq*4+3)*BST+n] = l;
            }
        }
        __syncthreads();

        const int moff = wm * 64, noff = wn * 32;
#pragma unroll
        for (int ks = 0; ks < KT / 8; ks++) {
            const int kr = ks * 8 + t4;
            uint32_t afH[4][4], afL[4][4], bfH[4][2], bfL[4][2];
#pragma unroll
            for (int mt = 0; mt < 4; mt++) {
                int mb = moff + mt * 16 + g;
                afH[mt][0] = AsH[kr * SST + mb];
                afH[mt][1] = AsH[kr * SST + mb + 8];
                afH[mt][2] = AsH[(kr + 4) * SST + mb];
                afH[mt][3] = AsH[(kr + 4) * SST + mb + 8];
                afL[mt][0] = AsL[kr * SST + mb];
                afL[mt][1] = AsL[kr * SST + mb + 8];
                afL[mt][2] = AsL[(kr + 4) * SST + mb];
                afL[mt][3] = AsL[(kr + 4) * SST + mb + 8];
            }
#pragma unroll
            for (int nt = 0; nt < 4; nt++) {
                int nb = noff + nt * 8 + g;
                bfH[nt][0] = BsH[kr * BST + nb];
                bfH[nt][1] = BsH[(kr + 4) * BST + nb];
                bfL[nt][0] = BsL[kr * BST + nb];
                bfL[nt][1] = BsL[(kr + 4) * BST + nb];
            }
#pragma unroll
            for (int mt = 0; mt < 4; mt++)
#pragma unroll
                for (int nt = 0; nt < 4; nt++) {
                    mma_tf32(acc[mt][nt], afH[mt], bfL[nt]);
                    mma_tf32(acc[mt][nt], afL[mt], bfH[nt]);
                    mma_tf32(acc[mt][nt], afH[mt], bfH[nt]);
                }
        }
        __syncthreads();
    }

    // ---- epilogue ----
#pragma unroll
    for (int mt = 0; mt < 4; mt++) {
        int m0 = bm + wm * 64 + mt * 16 + g;
#pragma unroll
        for (int nt = 0; nt < 4; nt++) {
            int n0 = bn + wn * 32 + nt * 8 + t4 * 2;
            if (n0 < N) {
                float b0v = bias ? bias[n0] : 0.f;
                float b1v = bias ? bias[n0 + 1] : 0.f;
                float o0 = acc[mt][nt][0] * alpha + b0v;
                float o1 = acc[mt][nt][1] * alpha + b1v;
                float o2 = acc[mt][nt][2] * alpha + b0v;
                float o3 = acc[mt][nt][3] * alpha + b1v;
                if (relu) {
                    o0 = fmaxf(o0, 0.f); o1 = fmaxf(o1, 0.f);
                    o2 = fmaxf(o2, 0.f); o3 = fmaxf(o3, 0.f);
                }
                C[(long long)m0 * N + n0] = o0;
                C[(long long)m0 * N + n0 + 1] = o1;
                C[(long long)(m0 + 8) * N + n0] = o2;
                C[(long long)(m0 + 8) * N + n0 + 1] = o3;
            }
        }
    }
}

// =====================================================================
// MoE expert GEMM 1 (gathered rows): H1 = relu(X[toks] @ W1 + b1)
// =====================================================================
__global__ void __launch_bounds__(256) moe_mma1_kernel(
    const float* __restrict__ X, const float* __restrict__ W,
    const float* __restrict__ bias, float* __restrict__ H1,
    const int* __restrict__ list, const int* __restrict__ cnt)
{
    constexpr int SST = 137, BST = 136;
    const int nrows = *cnt;
    const int bm = blockIdx.y * 128, bn = blockIdx.x * 128;
    if (bm >= nrows) return;
    __shared__ uint32_t AsH[KT * SST];
    __shared__ uint32_t AsL[KT * SST];
    __shared__ uint32_t BsH[KT * BST];
    __shared__ uint32_t BsL[KT * BST];
    __shared__ int toks[128];
    const int tid = threadIdx.x;
    const int lane = tid & 31, warp = tid >> 5;
    const int wm = warp >> 2, wn = warp & 3;
    const int g = lane >> 2, t4 = lane & 3;
    if (tid < 128) {
        int gr = bm + tid;
        toks[tid] = (gr < nrows) ? (list[gr] >> 1) : 0;
    }
    __syncthreads();

    float acc[4][4][4];
#pragma unroll
    for (int i = 0; i < 4; i++)
#pragma unroll
        for (int j = 0; j < 4; j++)
#pragma unroll
            for (int q = 0; q < 4; q++) acc[i][j][q] = 0.f;

    for (int k0 = 0; k0 < Dm; k0 += KT) {
#pragma unroll
        for (int i = 0; i < 2; i++) {
            int fv = tid + i * 256;
            int m = fv >> 2, kq = fv & 3;
            const float4 v = *(const float4*)&X[(long long)toks[m] * Dm + k0 + kq * 4];
            uint32_t h, l;
            split_tf(v.x, h, l); AsH[(kq*4+0)*SST+m] = h; AsL[(kq*4+0)*SST+m] = l;
            split_tf(v.y, h, l); AsH[(kq*4+1)*SST+m] = h; AsL[(kq*4+1)*SST+m] = l;
            split_tf(v.z, h, l); AsH[(kq*4+2)*SST+m] = h; AsL[(kq*4+2)*SST+m] = l;
            split_tf(v.w, h, l); AsH[(kq*4+3)*SST+m] = h; AsL[(kq*4+3)*SST+m] = l;
        }
#pragma unroll
        for (int i = 0; i < 2; i++) {
            int fv = tid + i * 256;
            int kk = fv >> 5, nq = fv & 31;
            const float4 v = *(const float4*)&W[(long long)(k0 + kk) * FF + bn + nq * 4];
            uint4 th, tl;
            split_tf(v.x, th.x, tl.x);
            split_tf(v.y, th.y, tl.y);
            split_tf(v.z, th.z, tl.z);
            split_tf(v.w, th.w, tl.w);
            *(uint4*)&BsH[kk * BST + nq * 4] = th;
            *(uint4*)&BsL[kk * BST + nq * 4] = tl;
        }
        __syncthreads();
        const int moff = wm * 64, noff = wn * 32;
#pragma unroll
        for (int ks = 0; ks < KT / 8; ks++) {
            const int kr = ks * 8 + t4;
            uint32_t afH[4][4], afL[4][4], bfH[4][2], bfL[4][2];
#pragma unroll
            for (int mt = 0; mt < 4; mt++) {
                int mb = moff + mt * 16 + g;
                afH[mt][0] = AsH[kr * SST + mb];
                afH[mt][1] = AsH[kr * SST + mb + 8];
                afH[mt][2] = AsH[(kr + 4) * SST + mb];
                afH[mt][3] = AsH[(kr + 4) * SST + mb + 8];
                afL[mt][0] = AsL[kr * SST + mb];
                afL[mt][1] = AsL[kr * SST + mb + 8];
                afL[mt][2] = AsL[(kr + 4) * SST + mb];
                afL[mt][3] = AsL[(kr + 4) * SST + mb + 8];
            }
#pragma unroll
            for (int nt = 0; nt < 4; nt++) {
                int nb = noff + nt * 8 + g;
                bfH[nt][0] = BsH[kr * BST + nb];
                bfH[nt][1] = BsH[(kr + 4) * BST + nb];
                bfL[nt][0] = BsL[kr * BST + nb];
                bfL[nt][1] = BsL[(kr + 4) * BST + nb];
            }
#pragma unroll
            for (int mt = 0; mt < 4; mt++)
#pragma unroll
                for (int nt = 0; nt < 4; nt++) {
                    mma_tf32(acc[mt][nt], afH[mt], bfL[nt]);
                    mma_tf32(acc[mt][nt], afL[mt], bfH[nt]);
                    mma_tf32(acc[mt][nt], afH[mt], bfH[nt]);
                }
        }
        __syncthreads();
    }

#pragma unroll
    for (int mt = 0; mt < 4; mt++) {
        int lr = wm * 64 + mt * 16 + g;
#pragma unroll
        for (int nt = 0; nt < 4; nt++) {
            int n0 = bn + wn * 32 + nt * 8 + t4 * 2;
            float b0v = bias[n0], b1v = bias[n0 + 1];
            if (bm + lr < nrows) {
                H1[(long long)(bm + lr) * FF + n0]     = fmaxf(acc[mt][nt][0] + b0v, 0.f);
                H1[(long long)(bm + lr) * FF + n0 + 1] = fmaxf(acc[mt][nt][1] + b1v, 0.f);
            }
            if (bm + lr + 8 < nrows) {
                H1[(long long)(bm + lr + 8) * FF + n0]     = fmaxf(acc[mt][nt][2] + b0v, 0.f);
                H1[(long long)(bm + lr + 8) * FF + n0 + 1] = fmaxf(acc[mt][nt][3] + b1v, 0.f);
            }
        }
    }
}

// =====================================================================
// MoE expert GEMM 2 (scatter): out_slot[token] = w * (H1 @ W2 + b2)
// =====================================================================
__global__ void __launch_bounds__(256) moe_mma2_kernel(
    const float* __restrict__ H1, const float* __restrict__ W,
    const float* __restrict__ bias,
    float* __restrict__ out0, float* __restrict__ out1,
    const float* __restrict__ topw,
    const int* __restrict__ list, const int* __restrict__ cnt)
{
    constexpr int SST = 137, BST = 136;
    const int nrows = *cnt;
    const int bm = blockIdx.y * 128, bn = blockIdx.x * 128;
    if (bm >= nrows) return;
    __shared__ uint32_t AsH[KT * SST];
    __shared__ uint32_t AsL[KT * SST];
    __shared__ uint32_t BsH[KT * BST];
    __shared__ uint32_t BsL[KT * BST];
    __shared__ int ents[128];
    const int tid = threadIdx.x;
    const int lane = tid & 31, warp = tid >> 5;
    const int wm = warp >> 2, wn = warp & 3;
    const int g = lane >> 2, t4 = lane & 3;
    if (tid < 128) {
        int gr = bm + tid;
        ents[tid] = (gr < nrows) ? list[gr] : -1;
    }
    __syncthreads();

    float acc[4][4][4];
#pragma unroll
    for (int i = 0; i < 4; i++)
#pragma unroll
        for (int j = 0; j < 4; j++)
#pragma unroll
            for (int q = 0; q < 4; q++) acc[i][j][q] = 0.f;

    for (int k0 = 0; k0 < FF; k0 += KT) {
#pragma unroll
        for (int i = 0; i < 2; i++) {
            int fv = tid + i * 256;
            int m = fv >> 2, kq = fv & 3;
            const float4 v = *(const float4*)&H1[(long long)(bm + m) * FF + k0 + kq * 4];
            uint32_t h, l;
            split_tf(v.x, h, l); AsH[(kq*4+0)*SST+m] = h; AsL[(kq*4+0)*SST+m] = l;
            split_tf(v.y, h, l); AsH[(kq*4+1)*SST+m] = h; AsL[(kq*4+1)*SST+m] = l;
            split_tf(v.z, h, l); AsH[(kq*4+2)*SST+m] = h; AsL[(kq*4+2)*SST+m] = l;
            split_tf(v.w, h, l); AsH[(kq*4+3)*SST+m] = h; AsL[(kq*4+3)*SST+m] = l;
        }
#pragma unroll
        for (int i = 0; i < 2; i++) {
            int fv = tid + i * 256;
            int kk = fv >> 5, nq = fv & 31;
            const float4 v = *(const float4*)&W[(long long)(k0 + kk) * Dm + bn + nq * 4];
            uint4 th, tl;
            split_tf(v.x, th.x, tl.x);
            split_tf(v.y, th.y, tl.y);
            split_tf(v.z, th.z, tl.z);
            split_tf(v.w, th.w, tl.w);
            *(uint4*)&BsH[kk * BST + nq * 4] = th;
            *(uint4*)&BsL[kk * BST + nq * 4] = tl;
        }
        __syncthreads();
        const int moff = wm * 64, noff = wn * 32;
#pragma unroll
        for (int ks = 0; ks < KT / 8; ks++) {
            const int kr = ks * 8 + t4;
            uint32_t afH[4][4], afL[4][4], bfH[4][2], bfL[4][2];
#pragma unroll
            for (int mt = 0; mt < 4; mt++) {
                int mb = moff + mt * 16 + g;
                afH[mt][0] = AsH[kr * SST + mb];
                afH[mt][1] = AsH[kr * SST + mb + 8];
                afH[mt][2] = AsH[(kr + 4) * SST + mb];
                afH[mt][3] = AsH[(kr + 4) * SST + mb + 8];
                afL[mt][0] = AsL[kr * SST + mb];
                afL[mt][1] = AsL[kr * SST + mb + 8];
                afL[mt][2] = AsL[(kr + 4) * SST + mb];
                afL[mt][3] = AsL[(kr + 4) * SST + mb + 8];
            }
#pragma unroll
            for (int nt = 0; nt < 4; nt++) {
                int nb = noff + nt * 8 + g;
                bfH[nt][0] = BsH[kr * BST + nb];
                bfH[nt][1] = BsH[(kr + 4) * BST + nb];
                bfL[nt][0] = BsL[kr * BST + nb];
                bfL[nt][1] = BsL[(kr + 4) * BST + nb];
            }
#pragma unroll
            for (int mt = 0; mt < 4; mt++)
#pragma unroll
                for (int nt = 0; nt < 4; nt++) {
                    mma_tf32(acc[mt][nt], afH[mt], bfL[nt]);
                    mma_tf32(acc[mt][nt], afL[mt], bfH[nt]);
                    mma_tf32(acc[mt][nt], afH[mt], bfH[nt]);
                }
        }
        __syncthreads();
    }

#pragma unroll
    for (int mt = 0; mt < 4; mt++) {
        int lr = wm * 64 + mt * 16 + g;
        int e0 = ents[lr], e2 = ents[lr + 8];
#pragma unroll
        for (int nt = 0; nt < 4; nt++) {
            int n0 = bn + wn * 32 + nt * 8 + t4 * 2;
            float b0v = bias[n0], b1v = bias[n0 + 1];
            if (e0 >= 0) {
                float w = topw[e0];
                float* o = (e0 & 1) ? out1 : out0;
                long long t = (long long)(e0 >> 1) * Dm;
                o[t + n0]     = w * (acc[mt][nt][0] + b0v);
                o[t + n0 + 1] = w * (acc[mt][nt][1] + b1v);
            }
            if (e2 >= 0) {
                float w = topw[e2];
                float* o = (e2 & 1) ? out1 : out0;
                long long t = (long long)(e2 >> 1) * Dm;
                o[t + n0]     = w * (acc[mt][nt][2] + b0v);
                o[t + n0 + 1] = w * (acc[mt][nt][3] + b1v);
            }
        }
    }
}

// ---------------- RoPE tables (double precision to match numpy f64) ----------------
__global__ void rope_init_kernel() {
    int idx = blockIdx.x * blockDim.x + threadIdx.x;
    if (idx >= Sn * HD) return;
    int s = idx >> 6;
    int j = idx & 63;
    int jj = j & 31;
    double inv = pow(10000.0, -((double)(2 * jj)) / 64.0);
    double ang = (double)s * inv;
    g_cos[idx] = (float)cos(ang);
    g_sin[idx] = (float)sin(ang);
}

// ---------------- embedding gather ----------------
__global__ void embed_kernel(const int* __restrict__ ids, const float* __restrict__ table,
                             float* __restrict__ out) {
    int idx = blockIdx.x * blockDim.x + threadIdx.x;
    int t = idx >> 10;
    int d = idx & 1023;
    out[idx] = table[(long long)ids[t] * Dm + d];
}

// ---------------- fp32 scalar SGEMM (kept for the tiny gate GEMM, N=8) ----------------
__global__ void sgemm_kernel(const float* __restrict__ A, const float* __restrict__ W,
                             const float* __restrict__ bias, float* __restrict__ C,
                             int M, int N, int K) {
    const int tid = threadIdx.x;
    const int bm = blockIdx.y * 64, bn = blockIdx.x * 64;
    __shared__ float As[16][68];
    __shared__ float Ws[16][68];
    float acc[4][4] = {};
    const int ty = tid >> 4, tx = tid & 15;
    for (int k0 = 0; k0 < K; k0 += 16) {
#pragma unroll
        for (int i = 0; i < 4; i++) {
            int e = tid + i * 256;
            int r = e >> 4, kk = e & 15;
            int gr = bm + r, gk = k0 + kk;
            As[kk][r] = (gr < M && gk < K) ? A[(long long)gr * K + gk] : 0.f;
        }
#pragma unroll
        for (int i = 0; i < 4; i++) {
            int e = tid + i * 256;
            int kk = e >> 6, c = e & 63;
            int gk = k0 + kk, gc = bn + c;
            Ws[kk][c] = (gk < K && gc < N) ? W[(long long)gk * N + gc] : 0.f;
        }
        __syncthreads();
#pragma unroll
        for (int kk = 0; kk < 16; kk++) {
            float4 a4 = *(const float4*)&As[kk][ty * 4];
            float4 b4 = *(const float4*)&Ws[kk][tx * 4];
            float av[4] = {a4.x, a4.y, a4.z, a4.w};
            float bv[4] = {b4.x, b4.y, b4.z, b4.w};
#pragma unroll
            for (int i = 0; i < 4; i++)
#pragma unroll
                for (int j = 0; j < 4; j++) acc[i][j] += av[i] * bv[j];
        }
        __syncthreads();
    }
#pragma unroll
    for (int i = 0; i < 4; i++) {
        int r = bm + ty * 4 + i;
        if (r >= M) continue;
#pragma unroll
        for (int j = 0; j < 4; j++) {
            int c = bn + tx * 4 + j;
            if (c >= N) continue;
            C[(long long)r * N + c] = acc[i][j] + (bias ? bias[c] : 0.f);
        }
    }
}

// ---------------- RoPE + [tok,D] -> [b,h,s,hd] permute ----------------
__global__ void rope_perm_kernel(const float* __restrict__ lin, float* __restrict__ out,
                                 int do_rope) {
    int idx = blockIdx.x * blockDim.x + threadIdx.x;
    int t = idx >> 10;
    int col = idx & 1023;
    int b = t >> 9;
    int s = t & 511;
    int h = col >> 6;
    int d = col & 63;
    float v = lin[idx];
    float o = v;
    if (do_rope) {
        float other = (d < 32) ? -lin[idx + 32] : lin[idx - 32];
        o = v * g_cos[s * 64 + d] + other * g_sin[s * 64 + d];
    }
    out[((long long)(b * Hn + h) * Sn + s) * HD + d] = o;
}

// ---------------- [b,h,s,hd] -> [tok,D] permute ----------------
__global__ void perm_back_kernel(const float* __restrict__ att, float* __restrict__ out) {
    int idx = blockIdx.x * blockDim.x + threadIdx.x;
    int d = idx & 63;
    int s = (idx >> 6) & 511;
    int h = (idx >> 15) & 15;
    int b = idx >> 19;
    out[(long long)(b * Sn + s) * Dm + h * HD + d] = att[idx];
}

// ---------------- row softmax with optional causal mask ----------------
__global__ void softmax_rows_kernel(float* __restrict__ sc, int causal) {
    int row = blockIdx.x;
    long long base = ((long long)blockIdx.y * Sn + row) * Sn;
    int tid = threadIdx.x;
    float v0 = sc[base + tid];
    float v1 = sc[base + tid + 256];
    if (causal) {
        if (tid > row) v0 = -1e9f;
        if (tid + 256 > row) v1 = -1e9f;
    }
    __shared__ float red[256];
    float m = fmaxf(v0, v1);
    red[tid] = m;
    __syncthreads();
    for (int s = 128; s > 0; s >>= 1) {
        if (tid < s) red[tid] = fmaxf(red[tid], red[tid + s]);
        __syncthreads();
    }
    m = red[0];
    __syncthreads();
    float e0 = expf(v0 - m), e1 = expf(v1 - m);
    red[tid] = e0 + e1;
    __syncthreads();
    for (int s = 128; s > 0; s >>= 1) {
        if (tid < s) red[tid] += red[tid + s];
        __syncthreads();
    }
    float inv = 1.f / red[0];
    sc[base + tid] = e0 * inv;
    sc[base + tid + 256] = e1 * inv;
}

// ---------------- fused residual add(+add2) + layernorm ----------------
__global__ void add_ln_kernel(const float* __restrict__ x, const float* __restrict__ a,
                              const float* __restrict__ a2,
                              const float* __restrict__ g, const float* __restrict__ b,
                              float* __restrict__ out) {
    int t = blockIdx.x;
    int tid = threadIdx.x;
    long long base = (long long)t * Dm;
    float v[4];
#pragma unroll
    for (int i = 0; i < 4; i++) {
        int c = tid + i * 256;
        float s = x[base + c] + a[base + c];
        if (a2) s += a2[base + c];
        v[i] = s;
    }
    __shared__ float red[256];
    red[tid] = v[0] + v[1] + v[2] + v[3];
    __syncthreads();
    for (int k = 128; k > 0; k >>= 1) {
        if (tid < k) red[tid] += red[tid + k];
        __syncthreads();
    }
    float mu = red[0] * (1.f / Dm);
    __syncthreads();
    float q = 0.f;
#pragma unroll
    for (int i = 0; i < 4; i++) { float d = v[i] - mu; q += d * d; }
    red[tid] = q;
    __syncthreads();
    for (int k = 128; k > 0; k >>= 1) {
        if (tid < k) red[tid] += red[tid + k];
        __syncthreads();
    }
    float var = red[0] * (1.f / Dm);
    float inv = rsqrtf(var + 1e-5f);
#pragma unroll
    for (int i = 0; i < 4; i++) {
        int c = tid + i * 256;
        out[base + c] = (v[i] - mu) * inv * g[c] + b[c];
    }
}

// ---------------- MoE gating: softmax over 8, top-2, renorm, route lists ----------------
__global__ void zero_cnt_kernel(int* c) { if (threadIdx.x < En) c[threadIdx.x] = 0; }

__global__ void gate_route_kernel(const float* __restrict__ logits, float* __restrict__ topw,
                                  int* __restrict__ list, int* __restrict__ cnt) {
    int t = blockIdx.x * blockDim.x + threadIdx.x;
    if (t >= TOK) return;
    float p[En];
    float m = -1e30f;
#pragma unroll
    for (int e = 0; e < En; e++) { p[e] = logits[t * En + e]; m = fmaxf(m, p[e]); }
    float s = 0.f;
#pragma unroll
    for (int e = 0; e < En; e++) { p[e] = expf(p[e] - m); s += p[e]; }
    float invs = 1.f / s;
#pragma unroll
    for (int e = 0; e < En; e++) p[e] *= invs;
    int i0 = 0;
#pragma unroll
    for (int e = 1; e < En; e++) if (p[e] > p[i0]) i0 = e;
    int i1 = (i0 == 0) ? 1 : 0;
#pragma unroll
    for (int e = 0; e < En; e++) if (e != i0 && p[e] > p[i1]) i1 = e;
    float s2 = p[i0] + p[i1];
    topw[t * 2 + 0] = p[i0] / s2;
    topw[t * 2 + 1] = p[i1] / s2;
    int pos = atomicAdd(&cnt[i0], 1);
    list[i0 * TOK + pos] = t * 2 + 0;
    pos = atomicAdd(&cnt[i1], 1);
    list[i1 * TOK + pos] = t * 2 + 1;
}

// ================= host orchestration =================
struct DevPtrs {
    float *x, *y, *lin0, *lin1, *lin2, *q, *k, *v, *sc, *att, *att_t, *proj;
    float *h1, *moe0, *moe1, *gate, *topw;
    int *list, *cnt;
};

static void mgemm(const float* A, const float* B, const float* bias, float* C,
                  int M, int N, int K, int relu, float alpha = 1.f, int batch = 1,
                  long long sA = 0, long long sB = 0, long long sC = 0) {
    dim3 g((N + 127) / 128, M / 128, batch);
    mma_gemm_kernel<0><<<g, 256>>>(A, B, bias, C, M, N, K, relu, alpha, sA, sB, sC);
}

static void mgemm_nt(const float* A, const float* B, float* C,
                     int M, int N, int K, float alpha, int batch,
                     long long sA, long long sB, long long sC) {
    dim3 g((N + 127) / 128, M / 128, batch);
    mma_gemm_kernel<1><<<g, 256>>>(A, B, nullptr, C, M, N, K, 0, alpha, sA, sB, sC);
}

static void run_mha(DevPtrs& P, float* xio, const float* kvin,
                    const float* wqkv, const float* bqkv,
                    const float* wo, const float* bo,
                    const float* lng, const float* lnb, int causal) {
    mgemm(xio,  wqkv,               bqkv,          P.lin0, TOK, Dm, Dm, 0);
    mgemm(kvin, wqkv + Dm * Dm,     bqkv + Dm,     P.lin1, TOK, Dm, Dm, 0);
    mgemm(kvin, wqkv + 2 * Dm * Dm, bqkv + 2 * Dm, P.lin2, TOK, Dm, Dm, 0);
    int nb = (TOK * Dm) / 256;
    rope_perm_kernel<<<nb, 256>>>(P.lin0, P.q, 1);
    rope_perm_kernel<<<nb, 256>>>(P.lin1, P.k, 1);
    rope_perm_kernel<<<nb, 256>>>(P.lin2, P.v, 0);
    // scores = Q @ K^T * scale  (NT gemm, batched over B*H)
    mgemm_nt(P.q, P.k, P.sc, Sn, Sn, HD, 0.125f, Bn * Hn,
             (long long)Sn * HD, (long long)Sn * HD, (long long)Sn * Sn);
    softmax_rows_kernel<<<dim3(Sn, Bn * Hn), 256>>>(P.sc, causal);
    mgemm(P.sc, P.v, nullptr, P.att, Sn, HD, Sn, 0, 1.f, Bn * Hn,
          (long long)Sn * Sn, (long long)Sn * HD, (long long)Sn * HD);
    perm_back_kernel<<<nb, 256>>>(P.att, P.att_t);
    mgemm(P.att_t, wo, bo, P.proj, TOK, Dm, Dm, 0);
    add_ln_kernel<<<TOK, 256>>>(xio, P.proj, nullptr, lng, lnb, xio);
}

static void run_moe(DevPtrs& P, float* xio, const float* gw, const float* gb,
                    const float* w1, const float* b1, const float* w2, const float* b2,
                    const float* lng, const float* lnb) {
    // gate logits in exact fp32 (routing decisions must not flip)
    sgemm_kernel<<<dim3(1, TOK / 64), 256>>>(xio, gw, gb, P.gate, TOK, En, Dm);
    zero_cnt_kernel<<<1, 32>>>(P.cnt);
    gate_route_kernel<<<TOK / 256, 256>>>(P.gate, P.topw, P.list, P.cnt);
    for (int e = 0; e < En; e++) {
        moe_mma1_kernel<<<dim3(FF / 128, TOK / 128), 256>>>(
            xio, w1 + (long long)e * Dm * FF, b1 + e * FF, P.h1,
            P.list + e * TOK, P.cnt + e);
        moe_mma2_kernel<<<dim3(Dm / 128, TOK / 128), 256>>>(
            P.h1, w2 + (long long)e * FF * Dm, b2 + e * Dm, P.moe0, P.moe1, P.topw,
            P.list + e * TOK, P.cnt + e);
    }
    add_ln_kernel<<<TOK, 256>>>(xio, P.moe0, P.moe1, lng, lnb, xio);
}

extern "C" void kernel_launch(void* const* d_in, const int* in_sizes, int n_in,
                              void* d_out, int out_size) {
    (void)in_sizes; (void)n_in; (void)out_size;
    const int*   src           = (const int*)  d_in[0];
    const int*   tgt           = (const int*)  d_in[1];
    const float* emb_src       = (const float*)d_in[2];
    const float* emb_tgt       = (const float*)d_in[3];
    const float* enc_wqkv      = (const float*)d_in[4];
    const float* enc_bqkv      = (const float*)d_in[5];
    const float* enc_wo        = (const float*)d_in[6];
    const float* enc_bo        = (const float*)d_in[7];
    const float* enc_gate_w    = (const float*)d_in[8];
    const float* enc_gate_b    = (const float*)d_in[9];
    const float* enc_w1        = (const float*)d_in[10];
    const float* enc_b1        = (const float*)d_in[11];
    const float* enc_w2        = (const float*)d_in[12];
    const float* enc_b2        = (const float*)d_in[13];
    const float* enc_ln        = (const float*)d_in[14];
    const float* dec_self_wqkv = (const float*)d_in[15];
    const float* dec_self_bqkv = (const float*)d_in[16];
    const float* dec_self_wo   = (const float*)d_in[17];
    const float* dec_self_bo   = (const float*)d_in[18];
    const float* dec_cross_wqkv= (const float*)d_in[19];
    const float* dec_cross_bqkv= (const float*)d_in[20];
    const float* dec_cross_wo  = (const float*)d_in[21];
    const float* dec_cross_bo  = (const float*)d_in[22];
    const float* dec_gate_w    = (const float*)d_in[23];
    const float* dec_gate_b    = (const float*)d_in[24];
    const float* dec_w1        = (const float*)d_in[25];
    const float* dec_b1        = (const float*)d_in[26];
    const float* dec_w2        = (const float*)d_in[27];
    const float* dec_b2        = (const float*)d_in[28];
    const float* dec_ln        = (const float*)d_in[29];
    const float* final_w       = (const float*)d_in[30];
    const float* final_b       = (const float*)d_in[31];
    float* out = (float*)d_out;

    DevPtrs P;
    cudaGetSymbolAddress((void**)&P.x, g_x);
    cudaGetSymbolAddress((void**)&P.y, g_y);
    cudaGetSymbolAddress((void**)&P.lin0, g_lin0);
    cudaGetSymbolAddress((void**)&P.lin1, g_lin1);
    cudaGetSymbolAddress((void**)&P.lin2, g_lin2);
    cudaGetSymbolAddress((void**)&P.q, g_q);
    cudaGetSymbolAddress((void**)&P.k, g_k);
    cudaGetSymbolAddress((void**)&P.v, g_v);
    cudaGetSymbolAddress((void**)&P.sc, g_sc);
    cudaGetSymbolAddress((void**)&P.att, g_att);
    cudaGetSymbolAddress((void**)&P.att_t, g_att_t);
    cudaGetSymbolAddress((void**)&P.proj, g_proj);
    cudaGetSymbolAddress((void**)&P.h1, g_h1);
    cudaGetSymbolAddress((void**)&P.moe0, g_moe0);
    cudaGetSymbolAddress((void**)&P.moe1, g_moe1);
    cudaGetSymbolAddress((void**)&P.gate, g_gate);
    cudaGetSymbolAddress((void**)&P.topw, g_topw);
    cudaGetSymbolAddress((void**)&P.list, g_list);
    cudaGetSymbolAddress((void**)&P.cnt, g_cnt);

    rope_init_kernel<<<(Sn * HD) / 256, 256>>>();

    // ---------- encoder ----------
    embed_kernel<<<(TOK * Dm) / 256, 256>>>(src, emb_src, P.x);
    for (int l = 0; l < Ln; l++) {
        run_mha(P, P.x, P.x,
                enc_wqkv + (long long)l * 3 * Dm * Dm, enc_bqkv + l * 3 * Dm,
                enc_wo + (long long)l * Dm * Dm, enc_bo + l * Dm,
                enc_ln + ((l * 2 + 0) * 2 + 0) * Dm, enc_ln + ((l * 2 + 0) * 2 + 1) * Dm, 0);
        run_moe(P, P.x,
                enc_gate_w + l * Dm * En, enc_gate_b + l * En,
                enc_w1 + (long long)l * En * Dm * FF, enc_b1 + l * En * FF,
                enc_w2 + (long long)l * En * FF * Dm, enc_b2 + l * En * Dm,
                enc_ln + ((l * 2 + 1) * 2 + 0) * Dm, enc_ln + ((l * 2 + 1) * 2 + 1) * Dm);
    }

    // ---------- decoder ----------
    embed_kernel<<<(TOK * Dm) / 256, 256>>>(tgt, emb_tgt, P.y);
    for (int l = 0; l < Ln; l++) {
        run_mha(P, P.y, P.y,
                dec_self_wqkv + (long long)l * 3 * Dm * Dm, dec_self_bqkv + l * 3 * Dm,
                dec_self_wo + (long long)l * Dm * Dm, dec_self_bo + l * Dm,
                dec_ln + ((l * 3 + 0) * 2 + 0) * Dm, dec_ln + ((l * 3 + 0) * 2 + 1) * Dm, 1);
        run_mha(P, P.y, P.x,
                dec_cross_wqkv + (long long)l * 3 * Dm * Dm, dec_cross_bqkv + l * 3 * Dm,
                dec_cross_wo + (long long)l * Dm * Dm, dec_cross_bo + l * Dm,
                dec_ln + ((l * 3 + 1) * 2 + 0) * Dm, dec_ln + ((l * 3 + 1) * 2 + 1) * Dm, 0);
        run_moe(P, P.y,
                dec_gate_w + l * Dm * En, dec_gate_b + l * En,
                dec_w1 + (long long)l * En * Dm * FF, dec_b1 + l * En * FF,
                dec_w2 + (long long)l * En * FF * Dm, dec_b2 + l * En * Dm,
                dec_ln + ((l * 3 + 2) * 2 + 0) * Dm, dec_ln + ((l * 3 + 2) * 2 + 1) * Dm);
    }

    // ---------- final projection ----------
    mgemm(P.y, final_w, final_b, out, TOK, VT, Dm, 0);
}

// round 4
// speedup vs baseline: 2.3598x; 2.3426x over previous
#include <cuda_runtime.h>
#include <math.h>
#include <stdint.h>

// ---------------- problem constants ----------------
#define Bn   4
#define Sn   512
#define Dm   1024
#define Hn   16
#define HD   64
#define En   8
#define FF   2048
#define Ln   2
#define VT   32000
#define TOK  (Bn*Sn)      // 2048 tokens

#define KT   16           // K-tile
#define ASTR 20           // [m][k] smem stride (conflict-free: g*20+t4 distinct mod 32)
#define BSTR 136          // [k][n] smem stride (conflict-free: t4*8+g distinct mod 32)

// ---------------- device scratch (no allocations allowed) ----------------
__device__ float g_x[TOK*Dm];
__device__ float g_y[TOK*Dm];
__device__ float g_lin0[TOK*Dm];
__device__ float g_lin1[TOK*Dm];
__device__ float g_lin2[TOK*Dm];
__device__ float g_q[TOK*Dm];
__device__ float g_k[TOK*Dm];
__device__ float g_v[TOK*Dm];
__device__ float g_sc[(size_t)Bn*Hn*Sn*Sn];     // 67 MB scores
__device__ float g_att[TOK*Dm];
__device__ float g_att_t[TOK*Dm];
__device__ float g_proj[TOK*Dm];
__device__ float g_h1[(size_t)En*TOK*FF];       // 134 MB: per-expert H1 slices
__device__ float g_moe0[TOK*Dm];
__device__ float g_moe1[TOK*Dm];
__device__ float g_gate[TOK*En];
__device__ float g_topw[TOK*2];
__device__ int   g_list[En*TOK];
__device__ int   g_cnt[En];
__device__ float g_cos[Sn*HD];
__device__ float g_sin[Sn*HD];

// ---------------- tf32 / cp.async helpers ----------------
__device__ __forceinline__ uint32_t f2tf(float f) {
    uint32_t r;
    asm("cvt.rna.tf32.f32 %0, %1;" : "=r"(r) : "f"(f));
    return r;
}
__device__ __forceinline__ void sp(float v, uint32_t& h, uint32_t& l) {
    h = f2tf(v);
    l = f2tf(v - __uint_as_float(h));
}
__device__ __forceinline__ uint32_t smem_u32(const void* p) {
    return (uint32_t)__cvta_generic_to_shared(p);
}
__device__ __forceinline__ void cp16(uint32_t dst, const void* src) {
    asm volatile("cp.async.cg.shared.global [%0], [%1], 16;" :: "r"(dst), "l"(src));
}
__device__ __forceinline__ void cp16z(uint32_t dst, const void* src, bool ok) {
    int sz = ok ? 16 : 0;
    asm volatile("cp.async.cg.shared.global [%0], [%1], 16, %2;" :: "r"(dst), "l"(src), "r"(sz));
}
#define CP_COMMIT() asm volatile("cp.async.commit_group;")
#define CP_WAIT1()  asm volatile("cp.async.wait_group 1;")
#define CP_WAIT0()  asm volatile("cp.async.wait_group 0;")

__device__ __forceinline__ void mma_tf32(float* c, const uint32_t* a, const uint32_t* b) {
    asm volatile(
        "mma.sync.aligned.m16n8k8.row.col.f32.tf32.tf32.f32 "
        "{%0,%1,%2,%3}, {%4,%5,%6,%7}, {%8,%9}, {%0,%1,%2,%3};"
        : "+f"(c[0]), "+f"(c[1]), "+f"(c[2]), "+f"(c[3])
        : "r"(a[0]), "r"(a[1]), "r"(a[2]), "r"(a[3]), "r"(b[0]), "r"(b[1]));
}

// shared compute step for the [m][k]-A + B tiles (split to hi/lo on read)
#define MMA_COMPUTE_BODY(ASBUF, BRD0, BRD1)                                          \
    const int moff = wm * 64, noff = wn * 32;                                        \
    _Pragma("unroll")                                                                \
    for (int ks = 0; ks < KT / 8; ks++) {                                            \
        const int kr = ks * 8 + t4;                                                  \
        uint32_t afH[4][4], afL[4][4], bfH[4][2], bfL[4][2];                         \
        _Pragma("unroll")                                                            \
        for (int mt = 0; mt < 4; mt++) {                                             \
            int mb = moff + mt * 16 + g;                                             \
            sp(ASBUF[mb * ASTR + kr],           afH[mt][0], afL[mt][0]);             \
            sp(ASBUF[(mb + 8) * ASTR + kr],     afH[mt][1], afL[mt][1]);             \
            sp(ASBUF[mb * ASTR + kr + 4],       afH[mt][2], afL[mt][2]);             \
            sp(ASBUF[(mb + 8) * ASTR + kr + 4], afH[mt][3], afL[mt][3]);             \
        }                                                                            \
        _Pragma("unroll")                                                            \
        for (int nt = 0; nt < 4; nt++) {                                             \
            int nb = noff + nt * 8 + g;                                              \
            sp(BRD0, bfH[nt][0], bfL[nt][0]);                                        \
            sp(BRD1, bfH[nt][1], bfL[nt][1]);                                        \
        }                                                                            \
        _Pragma("unroll")                                                            \
        for (int mt = 0; mt < 4; mt++)                                               \
            _Pragma("unroll")                                                        \
            for (int nt = 0; nt < 4; nt++) {                                         \
                mma_tf32(acc[mt][nt], afH[mt], bfL[nt]);                             \
                mma_tf32(acc[mt][nt], afL[mt], bfH[nt]);                             \
                mma_tf32(acc[mt][nt], afH[mt], bfH[nt]);                             \
            }                                                                        \
    }

// =====================================================================
// Pipelined 3xTF32 GEMM: C = alpha*(A@B) + bias (opt relu)
// Block 128x128, KT=16, double-buffered cp.async.
// BT=0: B is [K,N] row-major.  BT=1: B is [N,K] row-major (NT).
// M %128==0, K %16==0. N guarded for BT=0 loads + epilogue.
// =====================================================================
template<int BT>
__global__ void __launch_bounds__(256) mma_gemm_pipe(
    const float* __restrict__ A, const float* __restrict__ B,
    const float* __restrict__ bias, float* __restrict__ C,
    int M, int N, int K, int relu, float alpha,
    long long sA, long long sB, long long sC)
{
    constexpr int BSZ = BT ? 128 * ASTR : KT * BSTR;
    A += (long long)blockIdx.z * sA;
    B += (long long)blockIdx.z * sB;
    C += (long long)blockIdx.z * sC;
    __shared__ float As[2][128 * ASTR];
    __shared__ float Bs[2][BSZ];
    const int tid  = threadIdx.x;
    const int lane = tid & 31;
    const int warp = tid >> 5;
    const int wm = warp >> 2, wn = warp & 3;
    const int g  = lane >> 2, t4 = lane & 3;
    const int bm = blockIdx.y * 128, bn = blockIdx.x * 128;

    float acc[4][4][4];
#pragma unroll
    for (int i = 0; i < 4; i++)
#pragma unroll
        for (int j = 0; j < 4; j++)
#pragma unroll
            for (int q = 0; q < 4; q++) acc[i][j][q] = 0.f;

    auto issue_tile = [&](int kt, int b) {
        long long k0 = (long long)kt * KT;
#pragma unroll
        for (int i = 0; i < 2; i++) {
            int c = tid + i * 256;
            int m = c >> 2, cq = c & 3;
            cp16(smem_u32(&As[b][m * ASTR + cq * 4]),
                 A + (long long)(bm + m) * K + k0 + cq * 4);
        }
        if (BT == 0) {
#pragma unroll
            for (int i = 0; i < 2; i++) {
                int c = tid + i * 256;
                int kk = c >> 5, nq = c & 31;
                int gc = bn + nq * 4;
                cp16z(smem_u32(&Bs[b][kk * BSTR + nq * 4]),
                      B + (long long)(k0 + kk) * N + gc, gc < N);
            }
        } else {
#pragma unroll
            for (int i = 0; i < 2; i++) {
                int c = tid + i * 256;
                int n = c >> 2, cq = c & 3;
                cp16(smem_u32(&Bs[b][n * ASTR + cq * 4]),
                     B + (long long)(bn + n) * K + k0 + cq * 4);
            }
        }
        CP_COMMIT();
    };

    const int nk = K / KT;
    issue_tile(0, 0);
    for (int kt = 0; kt < nk; kt++) {
        if (kt + 1 < nk) { issue_tile(kt + 1, (kt + 1) & 1); CP_WAIT1(); }
        else             { CP_WAIT0(); }
        __syncthreads();
        const float* __restrict__ Ab = As[kt & 1];
        const float* __restrict__ Bb = Bs[kt & 1];
        if (BT == 0) {
            MMA_COMPUTE_BODY(Ab, Bb[kr * BSTR + nb], Bb[(kr + 4) * BSTR + nb])
        } else {
            MMA_COMPUTE_BODY(Ab, Bb[nb * ASTR + kr], Bb[nb * ASTR + kr + 4])
        }
        __syncthreads();
    }

    // ---- epilogue ----
#pragma unroll
    for (int mt = 0; mt < 4; mt++) {
        int m0 = bm + wm * 64 + mt * 16 + g;
#pragma unroll
        for (int nt = 0; nt < 4; nt++) {
            int n0 = bn + wn * 32 + nt * 8 + t4 * 2;
            if (n0 < N) {
                float b0v = bias ? bias[n0] : 0.f;
                float b1v = bias ? bias[n0 + 1] : 0.f;
                float o0 = acc[mt][nt][0] * alpha + b0v;
                float o1 = acc[mt][nt][1] * alpha + b1v;
                float o2 = acc[mt][nt][2] * alpha + b0v;
                float o3 = acc[mt][nt][3] * alpha + b1v;
                if (relu) {
                    o0 = fmaxf(o0, 0.f); o1 = fmaxf(o1, 0.f);
                    o2 = fmaxf(o2, 0.f); o3 = fmaxf(o3, 0.f);
                }
                C[(long long)m0 * N + n0] = o0;
                C[(long long)m0 * N + n0 + 1] = o1;
                C[(long long)(m0 + 8) * N + n0] = o2;
                C[(long long)(m0 + 8) * N + n0 + 1] = o3;
            }
        }
    }
}

// =====================================================================
// MoE expert GEMM 1 (all experts concurrent, z=expert):
// H1[e] = relu(X[toks_e] @ W1[e] + b1[e])
// =====================================================================
__global__ void __launch_bounds__(256) moe_mma1_pipe(
    const float* __restrict__ X, const float* __restrict__ W1,
    const float* __restrict__ b1, float* __restrict__ H1,
    const int* __restrict__ list, const int* __restrict__ cnt)
{
    const int e = blockIdx.z;
    const int nrows = cnt[e];
    const int bm = blockIdx.y * 128, bn = blockIdx.x * 128;
    if (bm >= nrows) return;
    const float* __restrict__ W = W1 + (long long)e * Dm * FF;
    const float* __restrict__ bias = b1 + e * FF;
    float* __restrict__ H = H1 + (size_t)e * TOK * FF;
    const int* __restrict__ lst = list + e * TOK;

    __shared__ float As[2][128 * ASTR];
    __shared__ float Bs[2][KT * BSTR];
    __shared__ int toks[128];
    const int tid = threadIdx.x;
    const int lane = tid & 31, warp = tid >> 5;
    const int wm = warp >> 2, wn = warp & 3;
    const int g = lane >> 2, t4 = lane & 3;
    if (tid < 128) {
        int gr = bm + tid;
        toks[tid] = (gr < nrows) ? (lst[gr] >> 1) : 0;
    }
    __syncthreads();

    float acc[4][4][4];
#pragma unroll
    for (int i = 0; i < 4; i++)
#pragma unroll
        for (int j = 0; j < 4; j++)
#pragma unroll
            for (int q = 0; q < 4; q++) acc[i][j][q] = 0.f;

    auto issue_tile = [&](int kt, int b) {
        long long k0 = (long long)kt * KT;
#pragma unroll
        for (int i = 0; i < 2; i++) {
            int c = tid + i * 256;
            int m = c >> 2, cq = c & 3;
            cp16(smem_u32(&As[b][m * ASTR + cq * 4]),
                 X + (long long)toks[m] * Dm + k0 + cq * 4);
        }
#pragma unroll
        for (int i = 0; i < 2; i++) {
            int c = tid + i * 256;
            int kk = c >> 5, nq = c & 31;
            cp16(smem_u32(&Bs[b][kk * BSTR + nq * 4]),
                 W + (long long)(k0 + kk) * FF + bn + nq * 4);
        }
        CP_COMMIT();
    };

    const int nk = Dm / KT;
    issue_tile(0, 0);
    for (int kt = 0; kt < nk; kt++) {
        if (kt + 1 < nk) { issue_tile(kt + 1, (kt + 1) & 1); CP_WAIT1(); }
        else             { CP_WAIT0(); }
        __syncthreads();
        const float* __restrict__ Ab = As[kt & 1];
        const float* __restrict__ Bb = Bs[kt & 1];
        MMA_COMPUTE_BODY(Ab, Bb[kr * BSTR + nb], Bb[(kr + 4) * BSTR + nb])
        __syncthreads();
    }

#pragma unroll
    for (int mt = 0; mt < 4; mt++) {
        int lr = wm * 64 + mt * 16 + g;
#pragma unroll
        for (int nt = 0; nt < 4; nt++) {
            int n0 = bn + wn * 32 + nt * 8 + t4 * 2;
            float b0v = bias[n0], b1v = bias[n0 + 1];
            if (bm + lr < nrows) {
                H[(size_t)(bm + lr) * FF + n0]     = fmaxf(acc[mt][nt][0] + b0v, 0.f);
                H[(size_t)(bm + lr) * FF + n0 + 1] = fmaxf(acc[mt][nt][1] + b1v, 0.f);
            }
            if (bm + lr + 8 < nrows) {
                H[(size_t)(bm + lr + 8) * FF + n0]     = fmaxf(acc[mt][nt][2] + b0v, 0.f);
                H[(size_t)(bm + lr + 8) * FF + n0 + 1] = fmaxf(acc[mt][nt][3] + b1v, 0.f);
            }
        }
    }
}

// =====================================================================
// MoE expert GEMM 2 (all experts concurrent, z=expert, scatter):
// out_slot[token] = w * (H1[e] @ W2[e] + b2[e])
// =====================================================================
__global__ void __launch_bounds__(256) moe_mma2_pipe(
    const float* __restrict__ H1, const float* __restrict__ W2,
    const float* __restrict__ b2,
    float* __restrict__ out0, float* __restrict__ out1,
    const float* __restrict__ topw,
    const int* __restrict__ list, const int* __restrict__ cnt)
{
    const int e = blockIdx.z;
    const int nrows = cnt[e];
    const int bm = blockIdx.y * 128, bn = blockIdx.x * 128;
    if (bm >= nrows) return;
    const float* __restrict__ W = W2 + (long long)e * FF * Dm;
    const float* __restrict__ bias = b2 + e * Dm;
    const float* __restrict__ H = H1 + (size_t)e * TOK * FF;
    const int* __restrict__ lst = list + e * TOK;

    __shared__ float As[2][128 * ASTR];
    __shared__ float Bs[2][KT * BSTR];
    __shared__ int ents[128];
    const int tid = threadIdx.x;
    const int lane = tid & 31, warp = tid >> 5;
    const int wm = warp >> 2, wn = warp & 3;
    const int g = lane >> 2, t4 = lane & 3;
    if (tid < 128) {
        int gr = bm + tid;
        ents[tid] = (gr < nrows) ? lst[gr] : -1;
    }
    __syncthreads();

    float acc[4][4][4];
#pragma unroll
    for (int i = 0; i < 4; i++)
#pragma unroll
        for (int j = 0; j < 4; j++)
#pragma unroll
            for (int q = 0; q < 4; q++) acc[i][j][q] = 0.f;

    auto issue_tile = [&](int kt, int b) {
        long long k0 = (long long)kt * KT;
#pragma unroll
        for (int i = 0; i < 2; i++) {
            int c = tid + i * 256;
            int m = c >> 2, cq = c & 3;
            cp16(smem_u32(&As[b][m * ASTR + cq * 4]),
                 H + (size_t)(bm + m) * FF + k0 + cq * 4);
        }
#pragma unroll
        for (int i = 0; i < 2; i++) {
            int c = tid + i * 256;
            int kk = c >> 5, nq = c & 31;
            cp16(smem_u32(&Bs[b][kk * BSTR + nq * 4]),
                 W + (long long)(k0 + kk) * Dm + bn + nq * 4);
        }
        CP_COMMIT();
    };

    const int nk = FF / KT;
    issue_tile(0, 0);
    for (int kt = 0; kt < nk; kt++) {
        if (kt + 1 < nk) { issue_tile(kt + 1, (kt + 1) & 1); CP_WAIT1(); }
        else             { CP_WAIT0(); }
        __syncthreads();
        const float* __restrict__ Ab = As[kt & 1];
        const float* __restrict__ Bb = Bs[kt & 1];
        MMA_COMPUTE_BODY(Ab, Bb[kr * BSTR + nb], Bb[(kr + 4) * BSTR + nb])
        __syncthreads();
    }

#pragma unroll
    for (int mt = 0; mt < 4; mt++) {
        int lr = wm * 64 + mt * 16 + g;
        int e0 = ents[lr], e2 = ents[lr + 8];
#pragma unroll
        for (int nt = 0; nt < 4; nt++) {
            int n0 = bn + wn * 32 + nt * 8 + t4 * 2;
            float b0v = bias[n0], b1v = bias[n0 + 1];
            if (e0 >= 0) {
                float w = topw[e0];
                float* o = (e0 & 1) ? out1 : out0;
                long long t = (long long)(e0 >> 1) * Dm;
                o[t + n0]     = w * (acc[mt][nt][0] + b0v);
                o[t + n0 + 1] = w * (acc[mt][nt][1] + b1v);
            }
            if (e2 >= 0) {
                float w = topw[e2];
                float* o = (e2 & 1) ? out1 : out0;
                long long t = (long long)(e2 >> 1) * Dm;
                o[t + n0]     = w * (acc[mt][nt][2] + b0v);
                o[t + n0 + 1] = w * (acc[mt][nt][3] + b1v);
            }
        }
    }
}

// ---------------- RoPE tables (double precision to match numpy f64) ----------------
__global__ void rope_init_kernel() {
    int idx = blockIdx.x * blockDim.x + threadIdx.x;
    if (idx >= Sn * HD) return;
    int s = idx >> 6;
    int j = idx & 63;
    int jj = j & 31;
    double inv = pow(10000.0, -((double)(2 * jj)) / 64.0);
    double ang = (double)s * inv;
    g_cos[idx] = (float)cos(ang);
    g_sin[idx] = (float)sin(ang);
}

// ---------------- embedding gather ----------------
__global__ void embed_kernel(const int* __restrict__ ids, const float* __restrict__ table,
                             float* __restrict__ out) {
    int idx = blockIdx.x * blockDim.x + threadIdx.x;
    int t = idx >> 10;
    int d = idx & 1023;
    out[idx] = table[(long long)ids[t] * Dm + d];
}

// ---------------- fp32 scalar SGEMM (tiny gate GEMM, N=8; exact routing) ----------------
__global__ void sgemm_kernel(const float* __restrict__ A, const float* __restrict__ W,
                             const float* __restrict__ bias, float* __restrict__ C,
                             int M, int N, int K) {
    const int tid = threadIdx.x;
    const int bm = blockIdx.y * 64, bn = blockIdx.x * 64;
    __shared__ float As[16][68];
    __shared__ float Ws[16][68];
    float acc[4][4] = {};
    const int ty = tid >> 4, tx = tid & 15;
    for (int k0 = 0; k0 < K; k0 += 16) {
#pragma unroll
        for (int i = 0; i < 4; i++) {
            int e = tid + i * 256;
            int r = e >> 4, kk = e & 15;
            int gr = bm + r, gk = k0 + kk;
            As[kk][r] = (gr < M && gk < K) ? A[(long long)gr * K + gk] : 0.f;
        }
#pragma unroll
        for (int i = 0; i < 4; i++) {
            int e = tid + i * 256;
            int kk = e >> 6, c = e & 63;
            int gk = k0 + kk, gc = bn + c;
            Ws[kk][c] = (gk < K && gc < N) ? W[(long long)gk * N + gc] : 0.f;
        }
        __syncthreads();
#pragma unroll
        for (int kk = 0; kk < 16; kk++) {
            float4 a4 = *(const float4*)&As[kk][ty * 4];
            float4 b4 = *(const float4*)&Ws[kk][tx * 4];
            float av[4] = {a4.x, a4.y, a4.z, a4.w};
            float bv[4] = {b4.x, b4.y, b4.z, b4.w};
#pragma unroll
            for (int i = 0; i < 4; i++)
#pragma unroll
                for (int j = 0; j < 4; j++) acc[i][j] += av[i] * bv[j];
        }
        __syncthreads();
    }
#pragma unroll
    for (int i = 0; i < 4; i++) {
        int r = bm + ty * 4 + i;
        if (r >= M) continue;
#pragma unroll
        for (int j = 0; j < 4; j++) {
            int c = bn + tx * 4 + j;
            if (c >= N) continue;
            C[(long long)r * N + c] = acc[i][j] + (bias ? bias[c] : 0.f);
        }
    }
}

// ---------------- RoPE + [tok,D] -> [b,h,s,hd] permute ----------------
__global__ void rope_perm_kernel(const float* __restrict__ lin, float* __restrict__ out,
                                 int do_rope) {
    int idx = blockIdx.x * blockDim.x + threadIdx.x;
    int t = idx >> 10;
    int col = idx & 1023;
    int b = t >> 9;
    int s = t & 511;
    int h = col >> 6;
    int d = col & 63;
    float v = lin[idx];
    float o = v;
    if (do_rope) {
        float other = (d < 32) ? -lin[idx + 32] : lin[idx - 32];
        o = v * g_cos[s * 64 + d] + other * g_sin[s * 64 + d];
    }
    out[((long long)(b * Hn + h) * Sn + s) * HD + d] = o;
}

// ---------------- [b,h,s,hd] -> [tok,D] permute ----------------
__global__ void perm_back_kernel(const float* __restrict__ att, float* __restrict__ out) {
    int idx = blockIdx.x * blockDim.x + threadIdx.x;
    int d = idx & 63;
    int s = (idx >> 6) & 511;
    int h = (idx >> 15) & 15;
    int b = idx >> 19;
    out[(long long)(b * Sn + s) * Dm + h * HD + d] = att[idx];
}

// ---------------- row softmax with optional causal mask ----------------
__global__ void softmax_rows_kernel(float* __restrict__ sc, int causal) {
    int row = blockIdx.x;
    long long base = ((long long)blockIdx.y * Sn + row) * Sn;
    int tid = threadIdx.x;
    float v0 = sc[base + tid];
    float v1 = sc[base + tid + 256];
    if (causal) {
        if (tid > row) v0 = -1e9f;
        if (tid + 256 > row) v1 = -1e9f;
    }
    __shared__ float red[256];
    float m = fmaxf(v0, v1);
    red[tid] = m;
    __syncthreads();
    for (int s = 128; s > 0; s >>= 1) {
        if (tid < s) red[tid] = fmaxf(red[tid], red[tid + s]);
        __syncthreads();
    }
    m = red[0];
    __syncthreads();
    float e0 = expf(v0 - m), e1 = expf(v1 - m);
    red[tid] = e0 + e1;
    __syncthreads();
    for (int s = 128; s > 0; s >>= 1) {
        if (tid < s) red[tid] += red[tid + s];
        __syncthreads();
    }
    float inv = 1.f / red[0];
    sc[base + tid] = e0 * inv;
    sc[base + tid + 256] = e1 * inv;
}

// ---------------- fused residual add(+add2) + layernorm ----------------
__global__ void add_ln_kernel(const float* __restrict__ x, const float* __restrict__ a,
                              const float* __restrict__ a2,
                              const float* __restrict__ g, const float* __restrict__ b,
                              float* __restrict__ out) {
    int t = blockIdx.x;
    int tid = threadIdx.x;
    long long base = (long long)t * Dm;
    float v[4];
#pragma unroll
    for (int i = 0; i < 4; i++) {
        int c = tid + i * 256;
        float s = x[base + c] + a[base + c];
        if (a2) s += a2[base + c];
        v[i] = s;
    }
    __shared__ float red[256];
    red[tid] = v[0] + v[1] + v[2] + v[3];
    __syncthreads();
    for (int k = 128; k > 0; k >>= 1) {
        if (tid < k) red[tid] += red[tid + k];
        __syncthreads();
    }
    float mu = red[0] * (1.f / Dm);
    __syncthreads();
    float q = 0.f;
#pragma unroll
    for (int i = 0; i < 4; i++) { float d = v[i] - mu; q += d * d; }
    red[tid] = q;
    __syncthreads();
    for (int k = 128; k > 0; k >>= 1) {
        if (tid < k) red[tid] += red[tid + k];
        __syncthreads();
    }
    float var = red[0] * (1.f / Dm);
    float inv = rsqrtf(var + 1e-5f);
#pragma unroll
    for (int i = 0; i < 4; i++) {
        int c = tid + i * 256;
        out[base + c] = (v[i] - mu) * inv * g[c] + b[c];
    }
}

// ---------------- MoE gating: softmax over 8, top-2, renorm, route lists ----------------
__global__ void zero_cnt_kernel(int* c) { if (threadIdx.x < En) c[threadIdx.x] = 0; }

__global__ void gate_route_kernel(const float* __restrict__ logits, float* __restrict__ topw,
                                  int* __restrict__ list, int* __restrict__ cnt) {
    int t = blockIdx.x * blockDim.x + threadIdx.x;
    if (t >= TOK) return;
    float p[En];
    float m = -1e30f;
#pragma unroll
    for (int e = 0; e < En; e++) { p[e] = logits[t * En + e]; m = fmaxf(m, p[e]); }
    float s = 0.f;
#pragma unroll
    for (int e = 0; e < En; e++) { p[e] = expf(p[e] - m); s += p[e]; }
    float invs = 1.f / s;
#pragma unroll
    for (int e = 0; e < En; e++) p[e] *= invs;
    int i0 = 0;
#pragma unroll
    for (int e = 1; e < En; e++) if (p[e] > p[i0]) i0 = e;
    int i1 = (i0 == 0) ? 1 : 0;
#pragma unroll
    for (int e = 0; e < En; e++) if (e != i0 && p[e] > p[i1]) i1 = e;
    float s2 = p[i0] + p[i1];
    topw[t * 2 + 0] = p[i0] / s2;
    topw[t * 2 + 1] = p[i1] / s2;
    int pos = atomicAdd(&cnt[i0], 1);
    list[i0 * TOK + pos] = t * 2 + 0;
    pos = atomicAdd(&cnt[i1], 1);
    list[i1 * TOK + pos] = t * 2 + 1;
}

// ================= host orchestration =================
struct DevPtrs {
    float *x, *y, *lin0, *lin1, *lin2, *q, *k, *v, *sc, *att, *att_t, *proj;
    float *h1, *moe0, *moe1, *gate, *topw;
    int *list, *cnt;
};

static void mgemm(const float* A, const float* B, const float* bias, float* C,
                  int M, int N, int K, int relu, float alpha = 1.f, int batch = 1,
                  long long sA = 0, long long sB = 0, long long sC = 0) {
    dim3 g((N + 127) / 128, M / 128, batch);
    mma_gemm_pipe<0><<<g, 256>>>(A, B, bias, C, M, N, K, relu, alpha, sA, sB, sC);
}

static void mgemm_nt(const float* A, const float* B, float* C,
                     int M, int N, int K, float alpha, int batch,
                     long long sA, long long sB, long long sC) {
    dim3 g((N + 127) / 128, M / 128, batch);
    mma_gemm_pipe<1><<<g, 256>>>(A, B, nullptr, C, M, N, K, 0, alpha, sA, sB, sC);
}

static void run_mha(DevPtrs& P, float* xio, const float* kvin,
                    const float* wqkv, const float* bqkv,
                    const float* wo, const float* bo,
                    const float* lng, const float* lnb, int causal) {
    mgemm(xio,  wqkv,               bqkv,          P.lin0, TOK, Dm, Dm, 0);
    mgemm(kvin, wqkv + Dm * Dm,     bqkv + Dm,     P.lin1, TOK, Dm, Dm, 0);
    mgemm(kvin, wqkv + 2 * Dm * Dm, bqkv + 2 * Dm, P.lin2, TOK, Dm, Dm, 0);
    int nb = (TOK * Dm) / 256;
    rope_perm_kernel<<<nb, 256>>>(P.lin0, P.q, 1);
    rope_perm_kernel<<<nb, 256>>>(P.lin1, P.k, 1);
    rope_perm_kernel<<<nb, 256>>>(P.lin2, P.v, 0);
    mgemm_nt(P.q, P.k, P.sc, Sn, Sn, HD, 0.125f, Bn * Hn,
             (long long)Sn * HD, (long long)Sn * HD, (long long)Sn * Sn);
    softmax_rows_kernel<<<dim3(Sn, Bn * Hn), 256>>>(P.sc, causal);
    mgemm(P.sc, P.v, nullptr, P.att, Sn, HD, Sn, 0, 1.f, Bn * Hn,
          (long long)Sn * Sn, (long long)Sn * HD, (long long)Sn * HD);
    perm_back_kernel<<<nb, 256>>>(P.att, P.att_t);
    mgemm(P.att_t, wo, bo, P.proj, TOK, Dm, Dm, 0);
    add_ln_kernel<<<TOK, 256>>>(xio, P.proj, nullptr, lng, lnb, xio);
}

static void run_moe(DevPtrs& P, float* xio, const float* gw, const float* gb,
                    const float* w1, const float* b1, const float* w2, const float* b2,
                    const float* lng, const float* lnb) {
    sgemm_kernel<<<dim3(1, TOK / 64), 256>>>(xio, gw, gb, P.gate, TOK, En, Dm);
    zero_cnt_kernel<<<1, 32>>>(P.cnt);
    gate_route_kernel<<<TOK / 256, 256>>>(P.gate, P.topw, P.list, P.cnt);
    moe_mma1_pipe<<<dim3(FF / 128, TOK / 128, En), 256>>>(
        xio, w1, b1, P.h1, P.list, P.cnt);
    moe_mma2_pipe<<<dim3(Dm / 128, TOK / 128, En), 256>>>(
        P.h1, w2, b2, P.moe0, P.moe1, P.topw, P.list, P.cnt);
    add_ln_kernel<<<TOK, 256>>>(xio, P.moe0, P.moe1, lng, lnb, xio);
}

extern "C" void kernel_launch(void* const* d_in, const int* in_sizes, int n_in,
                              void* d_out, int out_size) {
    (void)in_sizes; (void)n_in; (void)out_size;
    const int*   src           = (const int*)  d_in[0];
    const int*   tgt           = (const int*)  d_in[1];
    const float* emb_src       = (const float*)d_in[2];
    const float* emb_tgt       = (const float*)d_in[3];
    const float* enc_wqkv      = (const float*)d_in[4];
    const float* enc_bqkv      = (const float*)d_in[5];
    const float* enc_wo        = (const float*)d_in[6];
    const float* enc_bo        = (const float*)d_in[7];
    const float* enc_gate_w    = (const float*)d_in[8];
    const float* enc_gate_b    = (const float*)d_in[9];
    const float* enc_w1        = (const float*)d_in[10];
    const float* enc_b1        = (const float*)d_in[11];
    const float* enc_w2        = (const float*)d_in[12];
    const float* enc_b2        = (const float*)d_in[13];
    const float* enc_ln        = (const float*)d_in[14];
    const float* dec_self_wqkv = (const float*)d_in[15];
    const float* dec_self_bqkv = (const float*)d_in[16];
    const float* dec_self_wo   = (const float*)d_in[17];
    const float* dec_self_bo   = (const float*)d_in[18];
    const float* dec_cross_wqkv= (const float*)d_in[19];
    const float* dec_cross_bqkv= (const float*)d_in[20];
    const float* dec_cross_wo  = (const float*)d_in[21];
    const float* dec_cross_bo  = (const float*)d_in[22];
    const float* dec_gate_w    = (const float*)d_in[23];
    const float* dec_gate_b    = (const float*)d_in[24];
    const float* dec_w1        = (const float*)d_in[25];
    const float* dec_b1        = (const float*)d_in[26];
    const float* dec_w2        = (const float*)d_in[27];
    const float* dec_b2        = (const float*)d_in[28];
    const float* dec_ln        = (const float*)d_in[29];
    const float* final_w       = (const float*)d_in[30];
    const float* final_b       = (const float*)d_in[31];
    float* out = (float*)d_out;

    DevPtrs P;
    cudaGetSymbolAddress((void**)&P.x, g_x);
    cudaGetSymbolAddress((void**)&P.y, g_y);
    cudaGetSymbolAddress((void**)&P.lin0, g_lin0);
    cudaGetSymbolAddress((void**)&P.lin1, g_lin1);
    cudaGetSymbolAddress((void**)&P.lin2, g_lin2);
    cudaGetSymbolAddress((void**)&P.q, g_q);
    cudaGetSymbolAddress((void**)&P.k, g_k);
    cudaGetSymbolAddress((void**)&P.v, g_v);
    cudaGetSymbolAddress((void**)&P.sc, g_sc);
    cudaGetSymbolAddress((void**)&P.att, g_att);
    cudaGetSymbolAddress((void**)&P.att_t, g_att_t);
    cudaGetSymbolAddress((void**)&P.proj, g_proj);
    cudaGetSymbolAddress((void**)&P.h1, g_h1);
    cudaGetSymbolAddress((void**)&P.moe0, g_moe0);
    cudaGetSymbolAddress((void**)&P.moe1, g_moe1);
    cudaGetSymbolAddress((void**)&P.gate, g_gate);
    cudaGetSymbolAddress((void**)&P.topw, g_topw);
    cudaGetSymbolAddress((void**)&P.list, g_list);
    cudaGetSymbolAddress((void**)&P.cnt, g_cnt);

    rope_init_kernel<<<(Sn * HD) / 256, 256>>>();

    // ---------- encoder ----------
    embed_kernel<<<(TOK * Dm) / 256, 256>>>(src, emb_src, P.x);
    for (int l = 0; l < Ln; l++) {
        run_mha(P, P.x, P.x,
                enc_wqkv + (long long)l * 3 * Dm * Dm, enc_bqkv + l * 3 * Dm,
                enc_wo + (long long)l * Dm * Dm, enc_bo + l * Dm,
                enc_ln + ((l * 2 + 0) * 2 + 0) * Dm, enc_ln + ((l * 2 + 0) * 2 + 1) * Dm, 0);
        run_moe(P, P.x,
                enc_gate_w + l * Dm * En, enc_gate_b + l * En,
                enc_w1 + (long long)l * En * Dm * FF, enc_b1 + l * En * FF,
                enc_w2 + (long long)l * En * FF * Dm, enc_b2 + l * En * Dm,
                enc_ln + ((l * 2 + 1) * 2 + 0) * Dm, enc_ln + ((l * 2 + 1) * 2 + 1) * Dm);
    }

    // ---------- decoder ----------
    embed_kernel<<<(TOK * Dm) / 256, 256>>>(tgt, emb_tgt, P.y);
    for (int l = 0; l < Ln; l++) {
        run_mha(P, P.y, P.y,
                dec_self_wqkv + (long long)l * 3 * Dm * Dm, dec_self_bqkv + l * 3 * Dm,
                dec_self_wo + (long long)l * Dm * Dm, dec_self_bo + l * Dm,
                dec_ln + ((l * 3 + 0) * 2 + 0) * Dm, dec_ln + ((l * 3 + 0) * 2 + 1) * Dm, 1);
        run_mha(P, P.y, P.x,
                dec_cross_wqkv + (long long)l * 3 * Dm * Dm, dec_cross_bqkv + l * 3 * Dm,
                dec_cross_wo + (long long)l * Dm * Dm, dec_cross_bo + l * Dm,
                dec_ln + ((l * 3 + 1) * 2 + 0) * Dm, dec_ln + ((l * 3 + 1) * 2 + 1) * Dm, 0);
        run_moe(P, P.y,
                dec_gate_w + l * Dm * En, dec_gate_b + l * En,
                dec_w1 + (long long)l * En * Dm * FF, dec_b1 + l * En * FF,
                dec_w2 + (long long)l * En * FF * Dm, dec_b2 + l * En * Dm,
                dec_ln + ((l * 3 + 2) * 2 + 0) * Dm, dec_ln + ((l * 3 + 2) * 2 + 1) * Dm);
    }

    // ---------- final projection ----------
    mgemm(P.y, final_w, final_b, out, TOK, VT, Dm, 0);
}